// round 13
// baseline (speedup 1.0000x reference)
#include <cuda_runtime.h>
#include <cuda_bf16.h>
#include <math.h>
#include <stdint.h>

#define BB 4
#define SS 2048
#define DD 1024
#define DKK 128
#define MTOT (BB * SS)   // 8192
#define KSLICE 16
#define VSLICE 64

// ---------------------------------------------------------------------------
// Device scratch (allocation-free per harness rules)
// ---------------------------------------------------------------------------
__device__ __nv_bfloat16 g_xh[(size_t)MTOT * DD];
__device__ __nv_bfloat16 g_xl[(size_t)MTOT * DD];
__device__ __nv_bfloat16 g_wqkt_h[2 * DKK * DD], g_wqkt_l[2 * DKK * DD]; // [256,1024]
__device__ __nv_bfloat16 g_wvt_h[DD * DD],  g_wvt_l[DD * DD];
__device__ float g_bqk[2 * DKK];
__device__ __nv_bfloat16 g_qkh[(size_t)MTOT * 2 * DKK], g_qkl[(size_t)MTOT * 2 * DKK];
__device__ float g_v[(size_t)MTOT * DD];
__device__ __nv_bfloat16 g_vth[(size_t)BB * DD * SS], g_vtl[(size_t)BB * DD * SS];
__device__ float g_s[(size_t)BB * SS * SS];
__device__ __nv_bfloat16 g_ph[(size_t)BB * SS * SS], g_pl[(size_t)BB * SS * SS];
__device__ float g_xpart[KSLICE][BB][DD];
__device__ float g_vpart[VSLICE][BB][DD];
__device__ float g_xmean[BB * DD];
__device__ float g_vmean[BB * DD];
__device__ int   g_len[BB];

// ---------------------------------------------------------------------------
// mma.sync + cp.async + ldmatrix helpers (plain compute_103-safe PTX)
// ---------------------------------------------------------------------------
__device__ __forceinline__ uint32_t smem_u32(const void* p) {
    uint32_t a;
    asm("{ .reg .u64 t; cvta.to.shared.u64 t, %1; cvt.u32.u64 %0, t; }"
        : "=r"(a) : "l"(p));
    return a;
}
__device__ __forceinline__ void cp_async16(uint32_t dst, const void* src) {
    asm volatile("cp.async.cg.shared.global [%0], [%1], 16;"
                 :: "r"(dst), "l"(src) : "memory");
}
__device__ __forceinline__ void cp_commit() {
    asm volatile("cp.async.commit_group;" ::: "memory");
}
template<int N>
__device__ __forceinline__ void cp_wait() {
    asm volatile("cp.async.wait_group %0;" :: "n"(N) : "memory");
}
__device__ __forceinline__ void mma16816(float* c, const uint32_t* a, const uint32_t* b) {
    asm volatile(
        "mma.sync.aligned.m16n8k16.row.col.f32.bf16.bf16.f32 "
        "{%0,%1,%2,%3}, {%4,%5,%6,%7}, {%8,%9}, {%0,%1,%2,%3};"
        : "+f"(c[0]), "+f"(c[1]), "+f"(c[2]), "+f"(c[3])
        : "r"(a[0]), "r"(a[1]), "r"(a[2]), "r"(a[3]), "r"(b[0]), "r"(b[1]));
}
__device__ __forceinline__ void ldsm_x4(uint32_t* r, uint32_t addr) {
    asm volatile("ldmatrix.sync.aligned.m8n8.x4.shared.b16 {%0,%1,%2,%3}, [%4];"
                 : "=r"(r[0]), "=r"(r[1]), "=r"(r[2]), "=r"(r[3]) : "r"(addr));
}
__device__ __forceinline__ void ldsm_x2(uint32_t* r, uint32_t addr) {
    asm volatile("ldmatrix.sync.aligned.m8n8.x2.shared.b16 {%0,%1}, [%2];"
                 : "=r"(r[0]), "=r"(r[1]) : "r"(addr));
}

__device__ __forceinline__ void split1(float x, __nv_bfloat16& h, __nv_bfloat16& l) {
    h = __float2bfloat16(x);
    l = __float2bfloat16(x - __bfloat162float(h));
}

// ---------------------------------------------------------------------------
// bf16x3 GEMM on HMMA, 512 threads (4x4 warp grid, 32x32 warp tile).
// C[M,N] = alpha*(A @ B^T) (+ bias);  A bf16 (hi,lo) [M,*] row-stride lda,
// B bf16 (hi,lo) [N,*] row-stride ldb; K = reduction depth.
// CTA tile 128x128, K-chunk 32, 3-stage cp.async pipeline (R7-proven order).
// LENMODE: 0 none; 1 proj (skip (row0%2048)>=len); 2 scores; 3 P.V
// ---------------------------------------------------------------------------
#define ROWB 80
#define SM_TILE (128 * ROWB)            // 10240
#define STAGE_BYTES (4 * SM_TILE)       // 40960: Ah, Al, Bh, Bl
#define NSTAGE 3
#define SMEM_BYTES (NSTAGE * STAGE_BYTES)  // 122880
#define NTHR 512

template<bool SKIP_UPPER, bool CAUSAL_K, bool BIAS, bool OUT_SPLIT, int LENMODE>
__global__ void __launch_bounds__(NTHR, 1)
gemm_bf16x3(const __nv_bfloat16* __restrict__ Ah, const __nv_bfloat16* __restrict__ Al,
            const __nv_bfloat16* __restrict__ Bh, const __nv_bfloat16* __restrict__ Bl,
            const float* __restrict__ bias, float* __restrict__ C,
            __nv_bfloat16* __restrict__ Ch, __nv_bfloat16* __restrict__ Cl,
            int M, int N, int K, int lda, int ldb,
            long long sA, long long sB, long long sC, float alpha)
{
    if (SKIP_UPPER && blockIdx.x > blockIdx.y) return;

    const int row0 = blockIdx.y * 128;
    const int col0 = blockIdx.x * 128;

    int Keff = K;
    if (CAUSAL_K) { const int kl = (blockIdx.y + 1) * 128; Keff = kl < K ? kl : K; }

    if (LENMODE == 1) {
        const int b = row0 >> 11;
        if ((row0 & 2047) >= g_len[b]) return;
    } else if (LENMODE == 2) {
        const int L = g_len[blockIdx.z];
        if (row0 >= L || col0 >= L) return;
    } else if (LENMODE == 3) {
        const int L = g_len[blockIdx.z];
        if (row0 >= L) return;
        const int kcap = (L + 31) & ~31;
        if (kcap < Keff) Keff = kcap;
    }
    const int nchunk = Keff >> 5;   // K-chunk = 32

    extern __shared__ char smem[];

    const int tid = threadIdx.x;
    const int wid = tid >> 5, lane = tid & 31;
    const int wr = wid >> 2;        // 0..3  warp row (32 rows each)
    const int wc = wid & 3;         // 0..3  warp col (32 cols each)
    const int r4 = lane >> 2;
    const int c4 = lane & 3;

    Ah += (size_t)blockIdx.z * sA;  Al += (size_t)blockIdx.z * sA;
    Bh += (size_t)blockIdx.z * sB;  Bl += (size_t)blockIdx.z * sB;

    const uint32_t sb = smem_u32(smem);

    const int aRowSel = ((lane >> 3) & 1) * 8 + (lane & 7);  // row within 16
    const int aColSel = (lane >> 4) * 16;                    // 0/16 bytes
    const int bRowSel = lane & 7;
    const int bColSel = ((lane >> 3) & 1) * 16;
    const uint32_t aBase = (uint32_t)((wr * 32 + aRowSel) * ROWB + aColSel);
    const uint32_t bBase = (uint32_t)((wc * 32 + bRowSel) * ROWB + bColSel);

    // loader: per tile, ONE cp.async of 16B per thread (512 = 128 rows x 4 cols)
    auto ldstage = [&](int c, int s) {
        const long long kofs = (long long)c * 32;
        const uint32_t st = sb + s * STAGE_BYTES;
        const __nv_bfloat16* G[4] = { Ah, Al, Bh, Bl };
        const int row = tid >> 2;
        const int cb  = (tid & 3) * 16;
        #pragma unroll
        for (int t = 0; t < 4; t++) {
            const int r0 = (t < 2) ? row0 : col0;
            const int ld = (t < 2) ? lda : ldb;
            const char* src = (const char*)G[t] + ((size_t)(r0 + row) * ld + kofs) * 2 + cb;
            cp_async16(st + t * SM_TILE + row * ROWB + cb, src);
        }
        cp_commit();
    };

    float acc[2][4][4];
    #pragma unroll
    for (int i = 0; i < 2; i++)
        #pragma unroll
        for (int j = 0; j < 4; j++)
            #pragma unroll
            for (int r = 0; r < 4; r++) acc[i][j][r] = 0.0f;

    ldstage(0, 0);
    if (nchunk > 1) ldstage(1, 1); else cp_commit();

    for (int c = 0; c < nchunk; c++) {
        if (c + 2 < nchunk) ldstage(c + 2, (c + 2) % NSTAGE);
        else cp_commit();
        cp_wait<2>();
        __syncthreads();                  // stage c visible

        const uint32_t stg = sb + (c % NSTAGE) * STAGE_BYTES;
        #pragma unroll
        for (int ks = 0; ks < 2; ks++) {
            const uint32_t ko = ks * 32;

            uint32_t ah[2][4], al[2][4], bh[4][2], bl[4][2];
            #pragma unroll
            for (int nt = 0; nt < 4; nt++) {
                const uint32_t off = stg + bBase + nt * (8 * ROWB) + ko;
                ldsm_x2(bh[nt], off + 2 * SM_TILE);
                ldsm_x2(bl[nt], off + 3 * SM_TILE);
            }
            #pragma unroll
            for (int mt = 0; mt < 2; mt++) {
                const uint32_t off = stg + aBase + mt * (16 * ROWB) + ko;
                ldsm_x4(ah[mt], off);
                ldsm_x4(al[mt], off + SM_TILE);
            }

            // product-major issue: dependent MMAs 8 issues apart
            #pragma unroll
            for (int mt = 0; mt < 2; mt++)
                #pragma unroll
                for (int nt = 0; nt < 4; nt++)
                    mma16816(acc[mt][nt], ah[mt], bh[nt]);
            #pragma unroll
            for (int mt = 0; mt < 2; mt++)
                #pragma unroll
                for (int nt = 0; nt < 4; nt++)
                    mma16816(acc[mt][nt], ah[mt], bl[nt]);
            #pragma unroll
            for (int mt = 0; mt < 2; mt++)
                #pragma unroll
                for (int nt = 0; nt < 4; nt++)
                    mma16816(acc[mt][nt], al[mt], bh[nt]);
        }
        __syncthreads();                  // before buffer reuse
    }

    // epilogue
    #pragma unroll
    for (int mt = 0; mt < 2; mt++) {
        const int r = row0 + wr * 32 + mt * 16 + r4;
        #pragma unroll
        for (int nt = 0; nt < 4; nt++) {
            const int cidx = col0 + wc * 32 + nt * 8 + c4 * 2;
            float b0 = 0.f, b1 = 0.f;
            if (BIAS) { b0 = __ldg(bias + cidx); b1 = __ldg(bias + cidx + 1); }
            const float v00 = alpha * acc[mt][nt][0] + b0;
            const float v01 = alpha * acc[mt][nt][1] + b1;
            const float v10 = alpha * acc[mt][nt][2] + b0;
            const float v11 = alpha * acc[mt][nt][3] + b1;
            if (OUT_SPLIT) {
                __nv_bfloat16 h0, l0, h1, l1;
                split1(v00, h0, l0); split1(v01, h1, l1);
                *(__nv_bfloat162*)(Ch + (size_t)r * N + cidx) = __nv_bfloat162(h0, h1);
                *(__nv_bfloat162*)(Cl + (size_t)r * N + cidx) = __nv_bfloat162(l0, l1);
                split1(v10, h0, l0); split1(v11, h1, l1);
                *(__nv_bfloat162*)(Ch + (size_t)(r + 8) * N + cidx) = __nv_bfloat162(h0, h1);
                *(__nv_bfloat162*)(Cl + (size_t)(r + 8) * N + cidx) = __nv_bfloat162(l0, l1);
            } else {
                float* Cz = C + (size_t)blockIdx.z * sC;
                *(float2*)(Cz + (size_t)r * N + cidx)       = make_float2(v00, v01);
                *(float2*)(Cz + (size_t)(r + 8) * N + cidx) = make_float2(v10, v11);
            }
        }
    }
}

// ---------------------------------------------------------------------------
__global__ void compute_len(const int* __restrict__ mask)
{
    const int b = blockIdx.x;
    const int tid = threadIdx.x;
    __shared__ int red[256];
    int s = 0;
    for (int k = tid; k < SS; k += 256) s += mask[b * SS + k];
    red[tid] = s;
    __syncthreads();
    for (int o = 128; o > 0; o >>= 1) {
        if (tid < o) red[tid] += red[tid + o];
        __syncthreads();
    }
    if (tid == 0) g_len[b] = SS - red[0];
}

__global__ void build_bqk(const float* __restrict__ bq, const float* __restrict__ bk)
{
    const int i = threadIdx.x;
    g_bqk[i] = (i < DKK) ? bq[i] : bk[i - DKK];
}

// ---------------------------------------------------------------------------
__global__ void x_colmean_part(const float* __restrict__ x)
{
    const int d = blockIdx.x * 256 + threadIdx.x;
    const int b = blockIdx.y;
    const int sl = blockIdx.z;
    const float* xb = x + (size_t)b * SS * DD + (size_t)sl * 128 * DD + d;
    float s = 0.0f;
    #pragma unroll 8
    for (int k = 0; k < 128; k++) s += xb[(size_t)k * DD];
    g_xpart[sl][b][d] = s;
}
__global__ void x_colmean_finish()
{
    const int d = blockIdx.x * 256 + threadIdx.x;
    const int b = blockIdx.y;
    float s = 0.0f;
    #pragma unroll
    for (int sl = 0; sl < KSLICE; sl++) s += g_xpart[sl][b][d];
    g_xmean[b * DD + d] = s * (1.0f / (float)SS);
}

// ---------------------------------------------------------------------------
__global__ void vmean_part(const float* __restrict__ Wv)
{
    const int d = blockIdx.x * 256 + threadIdx.x;   // 0..1023
    const int sl = blockIdx.y;                      // 0..63
    float acc[BB] = {0.f, 0.f, 0.f, 0.f};
    #pragma unroll
    for (int kk = 0; kk < 16; kk++) {
        const int k = sl * 16 + kk;
        const float w = __ldg(Wv + (size_t)k * DD + d);
        #pragma unroll
        for (int b = 0; b < BB; b++) acc[b] += g_xmean[b * DD + k] * w;
    }
    #pragma unroll
    for (int b = 0; b < BB; b++) g_vpart[sl][b][d] = acc[b];
}
__global__ void vmean_finish(const float* __restrict__ bv)
{
    const int d = blockIdx.x * 256 + threadIdx.x;
    const int b = blockIdx.y;
    float s = __ldg(bv + d);
    #pragma unroll
    for (int sl = 0; sl < VSLICE; sl++) s += g_vpart[sl][b][d];
    g_vmean[b * DD + d] = s;
}

// ---------------------------------------------------------------------------
__global__ void split_fp32(const float* __restrict__ src,
                           __nv_bfloat16* __restrict__ hi, __nv_bfloat16* __restrict__ lo,
                           long long n4)
{
    const long long i = (long long)blockIdx.x * blockDim.x + threadIdx.x;
    if (i >= n4) return;
    float4 v = ((const float4*)src)[i];
    __nv_bfloat16 h0, h1, h2, h3, l0, l1, l2, l3;
    split1(v.x, h0, l0); split1(v.y, h1, l1); split1(v.z, h2, l2); split1(v.w, h3, l3);
    __nv_bfloat162* H = (__nv_bfloat162*)hi;
    __nv_bfloat162* L = (__nv_bfloat162*)lo;
    H[2 * i]     = __nv_bfloat162(h0, h1);
    H[2 * i + 1] = __nv_bfloat162(h2, h3);
    L[2 * i]     = __nv_bfloat162(l0, l1);
    L[2 * i + 1] = __nv_bfloat162(l2, l3);
}

// ---------------------------------------------------------------------------
__global__ void transpose_split(const float* __restrict__ in,
                                __nv_bfloat16* __restrict__ oh, __nv_bfloat16* __restrict__ ol,
                                int R, int C, long long sIn, long long sOut, int uselen)
{
    const int c0 = blockIdx.x * 32, r0 = blockIdx.y * 32;
    if (uselen && r0 >= g_len[blockIdx.z]) return;
    __shared__ float t[32][33];
    in += (size_t)blockIdx.z * sIn;
    oh += (size_t)blockIdx.z * sOut;
    ol += (size_t)blockIdx.z * sOut;
    const int tx = threadIdx.x & 31, ty = threadIdx.x >> 5;
    #pragma unroll
    for (int k = 0; k < 32; k += 8)
        t[ty + k][tx] = in[(size_t)(r0 + ty + k) * C + c0 + tx];
    __syncthreads();
    #pragma unroll
    for (int k = 0; k < 32; k += 8) {
        __nv_bfloat16 h, l;
        split1(t[tx][ty + k], h, l);
        oh[(size_t)(c0 + ty + k) * R + r0 + tx] = h;
        ol[(size_t)(c0 + ty + k) * R + r0 + tx] = l;
    }
}

// ---------------------------------------------------------------------------
__global__ void masked_softmax(const int* __restrict__ mask)
{
    const int q = blockIdx.x;
    const int b = blockIdx.y;
    if (mask[b * SS + q] != 0) return;

    const size_t off = ((size_t)b * SS + q) * SS;
    const float* row = g_s + off;
    __nv_bfloat16* ph = g_ph + off;
    __nv_bfloat16* pl = g_pl + off;
    const int tid = threadIdx.x;

    const int L   = g_len[b];
    const int cap = (L + 31) & ~31;

    __shared__ float red[256];

    float vals[8];
    float m = -INFINITY;
    #pragma unroll
    for (int it = 0; it < 8; it++) {
        const int k = tid + it * 256;
        float s = -INFINITY;
        if (k < cap) {
            const bool valid = (k <= q) && (mask[b * SS + k] == 0);
            s = valid ? row[k] : -INFINITY;
        }
        vals[it] = s;
        m = fmaxf(m, s);
    }
    red[tid] = m;
    __syncthreads();
    for (int o = 128; o > 0; o >>= 1) {
        if (tid < o) red[tid] = fmaxf(red[tid], red[tid + o]);
        __syncthreads();
    }
    m = red[0];
    __syncthreads();

    float sum = 0.0f;
    #pragma unroll
    for (int it = 0; it < 8; it++) {
        const float e = (vals[it] == -INFINITY) ? 0.0f : __expf(vals[it] - m);
        vals[it] = e;
        sum += e;
    }
    red[tid] = sum;
    __syncthreads();
    for (int o = 128; o > 0; o >>= 1) {
        if (tid < o) red[tid] += red[tid + o];
        __syncthreads();
    }
    const float inv = 1.0f / red[0];

    #pragma unroll
    for (int it = 0; it < 8; it++) {
        const int k = tid + it * 256;
        if (k < cap) {
            __nv_bfloat16 h, l;
            split1(vals[it] * inv, h, l);
            ph[k] = h;
            pl[k] = l;
        }
    }
}

// ---------------------------------------------------------------------------
__global__ void scatter_padded(const int* __restrict__ mask, float* __restrict__ out)
{
    const int q = blockIdx.x;
    const int b = blockIdx.y;
    if (mask[b * SS + q] == 0) return;
    const int tid = threadIdx.x;
    float* o = out + ((size_t)b * SS + q) * DD;
    const float* vm = g_vmean + b * DD;
    #pragma unroll
    for (int it = 0; it < 4; it++) o[tid + it * 256] = vm[tid + it * 256];
}

// ---------------------------------------------------------------------------
extern "C" void kernel_launch(void* const* d_in, const int* in_sizes, int n_in,
                              void* d_out, int out_size)
{
    const float* x    = (const float*)d_in[0];
    const int*   mask = (const int*)d_in[1];
    const float* Wq   = (const float*)d_in[2];
    const float* bq   = (const float*)d_in[3];
    const float* Wk   = (const float*)d_in[4];
    const float* bk   = (const float*)d_in[5];
    const float* Wv   = (const float*)d_in[6];
    const float* bv   = (const float*)d_in[7];
    float* out = (float*)d_out;

    cudaFuncSetAttribute(gemm_bf16x3<false, false, true, true, 1>,
                         cudaFuncAttributeMaxDynamicSharedMemorySize, SMEM_BYTES);
    cudaFuncSetAttribute(gemm_bf16x3<false, false, true, false, 1>,
                         cudaFuncAttributeMaxDynamicSharedMemorySize, SMEM_BYTES);
    cudaFuncSetAttribute(gemm_bf16x3<true, false, false, false, 2>,
                         cudaFuncAttributeMaxDynamicSharedMemorySize, SMEM_BYTES);
    cudaFuncSetAttribute(gemm_bf16x3<false, true, false, false, 3>,
                         cudaFuncAttributeMaxDynamicSharedMemorySize, SMEM_BYTES);

    __nv_bfloat16 *xh, *xl, *wqkth, *wqktl, *wvth, *wvtl;
    __nv_bfloat16 *qkh, *qkl, *vth, *vtl, *ph, *pl;
    float *v, *s, *bqk;
    cudaGetSymbolAddress((void**)&xh, g_xh);      cudaGetSymbolAddress((void**)&xl, g_xl);
    cudaGetSymbolAddress((void**)&wqkth, g_wqkt_h); cudaGetSymbolAddress((void**)&wqktl, g_wqkt_l);
    cudaGetSymbolAddress((void**)&wvth, g_wvt_h); cudaGetSymbolAddress((void**)&wvtl, g_wvt_l);
    cudaGetSymbolAddress((void**)&qkh, g_qkh);    cudaGetSymbolAddress((void**)&qkl, g_qkl);
    cudaGetSymbolAddress((void**)&v, g_v);
    cudaGetSymbolAddress((void**)&vth, g_vth);    cudaGetSymbolAddress((void**)&vtl, g_vtl);
    cudaGetSymbolAddress((void**)&s, g_s);
    cudaGetSymbolAddress((void**)&ph, g_ph);      cudaGetSymbolAddress((void**)&pl, g_pl);
    cudaGetSymbolAddress((void**)&bqk, g_bqk);

    const float scale = 1.0f / sqrtf((float)DKK);

    // 0. lengths; combined bias; xmean (2-stage); vmean (2-stage)
    compute_len<<<BB, 256>>>(mask);
    build_bqk<<<1, 2 * DKK>>>(bq, bk);
    x_colmean_part<<<dim3(DD / 256, BB, KSLICE), 256>>>(x);
    x_colmean_finish<<<dim3(DD / 256, BB), 256>>>();
    vmean_part<<<dim3(DD / 256, VSLICE), 256>>>(Wv);
    vmean_finish<<<dim3(DD / 256, BB), 256>>>(bv);

    // 1. split x into bf16 hi/lo
    {
        long long n4 = (long long)MTOT * DD / 4;
        split_fp32<<<(unsigned)((n4 + 255) / 256), 256>>>(x, xh, xl, n4);
    }
    // 2. transpose + split weights.  Wq -> rows 0..127 of WqkT, Wk -> 128..255
    transpose_split<<<dim3(DKK / 32, DD / 32, 1), 256>>>(Wq, wqkth, wqktl, DD, DKK, 0, 0, 0);
    transpose_split<<<dim3(DKK / 32, DD / 32, 1), 256>>>(Wk, wqkth + (size_t)DKK * DD,
                                                         wqktl + (size_t)DKK * DD, DD, DKK, 0, 0, 0);
    transpose_split<<<dim3(DD / 32, DD / 32, 1), 256>>>(Wv, wvth, wvtl, DD, DD, 0, 0, 0);

    // 3a. fused q|k projection: [8192, 256] = x @ [Wq|Wk]
    gemm_bf16x3<false, false, true, true, 1><<<dim3(2 * DKK / 128, MTOT / 128, 1), NTHR, SMEM_BYTES>>>(
        xh, xl, wqkth, wqktl, bqk, nullptr, qkh, qkl,
        MTOT, 2 * DKK, DD, DD, DD, 0, 0, 0, 1.0f);
    // 3b. v projection
    gemm_bf16x3<false, false, true, false, 1><<<dim3(DD / 128, MTOT / 128, 1), NTHR, SMEM_BYTES>>>(
        xh, xl, wvth, wvtl, bv, v, nullptr, nullptr,
        MTOT, DD, DD, DD, DD, 0, 0, 0, 1.0f);

    // 4. transpose+split v per batch (skip rows >= len)
    transpose_split<<<dim3(DD / 32, SS / 32, BB), 256>>>(
        v, vth, vtl, SS, DD, (long long)SS * DD, (long long)SS * DD, 1);

    // 5. scores = q @ k^T from the combined buffer, lower-triangle clipped
    gemm_bf16x3<true, false, false, false, 2><<<dim3(SS / 128, SS / 128, BB), NTHR, SMEM_BYTES>>>(
        qkh, qkl, qkh + DKK, qkl + DKK, nullptr, s, nullptr, nullptr,
        SS, SS, DKK, 2 * DKK, 2 * DKK,
        (long long)SS * 2 * DKK, (long long)SS * 2 * DKK, (long long)SS * SS, scale);

    // 6. masked softmax -> P (bf16 hi/lo), bounded to round_up(len,32)
    masked_softmax<<<dim3(SS, BB), 256>>>(mask);

    // 7. out = P @ V^T-layout, K truncated to min(causal, len); skip rows>=len
    gemm_bf16x3<false, true, false, false, 3><<<dim3(DD / 128, SS / 128, BB), NTHR, SMEM_BYTES>>>(
        ph, pl, vth, vtl, nullptr, out, nullptr, nullptr,
        SS, DD, SS, SS, SS,
        (long long)SS * SS, (long long)DD * SS, (long long)SS * DD, 1.0f);

    // 8. padded rows <- uniform attention
    scatter_padded<<<dim3(SS, BB), 256>>>(mask, out);
}

// round 14
// speedup vs baseline: 1.0377x; 1.0377x over previous
#include <cuda_runtime.h>
#include <cuda_bf16.h>
#include <math.h>
#include <stdint.h>

#define BB 4
#define SS 2048
#define DD 1024
#define DKK 128
#define MTOT (BB * SS)   // 8192
#define KSLICE 16
#define VSLICE 64

// ---------------------------------------------------------------------------
// Device scratch (allocation-free per harness rules)
// ---------------------------------------------------------------------------
__device__ __nv_bfloat16 g_xh[(size_t)MTOT * DD];
__device__ __nv_bfloat16 g_xl[(size_t)MTOT * DD];
__device__ __nv_bfloat16 g_wqkt_h[2 * DKK * DD], g_wqkt_l[2 * DKK * DD]; // [256,1024]
__device__ __nv_bfloat16 g_wvt_h[DD * DD],  g_wvt_l[DD * DD];
__device__ float g_bqk[2 * DKK];
__device__ __nv_bfloat16 g_qkh[(size_t)MTOT * 2 * DKK], g_qkl[(size_t)MTOT * 2 * DKK];
__device__ float g_v[(size_t)MTOT * DD];
__device__ __nv_bfloat16 g_vth[(size_t)BB * DD * SS], g_vtl[(size_t)BB * DD * SS];
__device__ float g_s[(size_t)BB * SS * SS];
__device__ __nv_bfloat16 g_ph[(size_t)BB * SS * SS], g_pl[(size_t)BB * SS * SS];
__device__ float g_xpart[KSLICE][BB][DD];
__device__ float g_vpart[VSLICE][BB][DD];
__device__ float g_xmean[BB * DD];
__device__ float g_vmean[BB * DD];
__device__ int   g_len[BB];

// ---------------------------------------------------------------------------
// mma.sync + cp.async + ldmatrix helpers (plain compute_103-safe PTX)
// ---------------------------------------------------------------------------
__device__ __forceinline__ uint32_t smem_u32(const void* p) {
    uint32_t a;
    asm("{ .reg .u64 t; cvta.to.shared.u64 t, %1; cvt.u32.u64 %0, t; }"
        : "=r"(a) : "l"(p));
    return a;
}
__device__ __forceinline__ void cp_async16(uint32_t dst, const void* src) {
    asm volatile("cp.async.cg.shared.global [%0], [%1], 16;"
                 :: "r"(dst), "l"(src) : "memory");
}
__device__ __forceinline__ void cp_commit() {
    asm volatile("cp.async.commit_group;" ::: "memory");
}
template<int N>
__device__ __forceinline__ void cp_wait() {
    asm volatile("cp.async.wait_group %0;" :: "n"(N) : "memory");
}
__device__ __forceinline__ void mma16816(float* c, const uint32_t* a, const uint32_t* b) {
    asm volatile(
        "mma.sync.aligned.m16n8k16.row.col.f32.bf16.bf16.f32 "
        "{%0,%1,%2,%3}, {%4,%5,%6,%7}, {%8,%9}, {%0,%1,%2,%3};"
        : "+f"(c[0]), "+f"(c[1]), "+f"(c[2]), "+f"(c[3])
        : "r"(a[0]), "r"(a[1]), "r"(a[2]), "r"(a[3]), "r"(b[0]), "r"(b[1]));
}
__device__ __forceinline__ void ldsm_x4(uint32_t* r, uint32_t addr) {
    asm volatile("ldmatrix.sync.aligned.m8n8.x4.shared.b16 {%0,%1,%2,%3}, [%4];"
                 : "=r"(r[0]), "=r"(r[1]), "=r"(r[2]), "=r"(r[3]) : "r"(addr));
}
__device__ __forceinline__ void ldsm_x2(uint32_t* r, uint32_t addr) {
    asm volatile("ldmatrix.sync.aligned.m8n8.x2.shared.b16 {%0,%1}, [%2];"
                 : "=r"(r[0]), "=r"(r[1]) : "r"(addr));
}

__device__ __forceinline__ void split1(float x, __nv_bfloat16& h, __nv_bfloat16& l) {
    h = __float2bfloat16(x);
    l = __float2bfloat16(x - __bfloat162float(h));
}

// ---------------------------------------------------------------------------
// bf16x3 GEMM on HMMA — R11-proven geometry (256 thr, 2x4 warps, 64x32 warp
// tile), 4-stage cp.async pipeline (prefetch-before-compute, cp_wait<3>).
// C[M,N] = alpha*(A @ B^T) (+ bias);  A bf16 (hi,lo) [M,*] row-stride lda,
// B bf16 (hi,lo) [N,*] row-stride ldb; K = reduction depth.
// LENMODE: 0 none; 1 proj (skip (row0%2048)>=len); 2 scores; 3 P.V
// ---------------------------------------------------------------------------
#define ROWB 80
#define SM_TILE (128 * ROWB)            // 10240
#define STAGE_BYTES (4 * SM_TILE)       // 40960: Ah, Al, Bh, Bl
#define NSTAGE 4
#define SMEM_BYTES (NSTAGE * STAGE_BYTES)  // 163840
#define NTHR 256

template<bool SKIP_UPPER, bool CAUSAL_K, bool BIAS, bool OUT_SPLIT, int LENMODE>
__global__ void __launch_bounds__(NTHR, 1)
gemm_bf16x3(const __nv_bfloat16* __restrict__ Ah, const __nv_bfloat16* __restrict__ Al,
            const __nv_bfloat16* __restrict__ Bh, const __nv_bfloat16* __restrict__ Bl,
            const float* __restrict__ bias, float* __restrict__ C,
            __nv_bfloat16* __restrict__ Ch, __nv_bfloat16* __restrict__ Cl,
            int M, int N, int K, int lda, int ldb,
            long long sA, long long sB, long long sC, float alpha)
{
    if (SKIP_UPPER && blockIdx.x > blockIdx.y) return;

    const int row0 = blockIdx.y * 128;
    const int col0 = blockIdx.x * 128;

    int Keff = K;
    if (CAUSAL_K) { const int kl = (blockIdx.y + 1) * 128; Keff = kl < K ? kl : K; }

    if (LENMODE == 1) {
        const int b = row0 >> 11;
        if ((row0 & 2047) >= g_len[b]) return;
    } else if (LENMODE == 2) {
        const int L = g_len[blockIdx.z];
        if (row0 >= L || col0 >= L) return;
    } else if (LENMODE == 3) {
        const int L = g_len[blockIdx.z];
        if (row0 >= L) return;
        const int kcap = (L + 31) & ~31;
        if (kcap < Keff) Keff = kcap;
    }
    const int nchunk = Keff >> 5;   // K-chunk = 32

    extern __shared__ char smem[];

    const int tid = threadIdx.x;
    const int wid = tid >> 5, lane = tid & 31;
    const int wr = wid >> 2;        // 0..1  warp row (64 rows)
    const int wc = wid & 3;         // 0..3  warp col (32 cols)
    const int r4 = lane >> 2;
    const int c4 = lane & 3;

    Ah += (size_t)blockIdx.z * sA;  Al += (size_t)blockIdx.z * sA;
    Bh += (size_t)blockIdx.z * sB;  Bl += (size_t)blockIdx.z * sB;

    const uint32_t sb = smem_u32(smem);

    const int aRowSel = ((lane >> 3) & 1) * 8 + (lane & 7);
    const int aColSel = (lane >> 4) * 16;
    const int bRowSel = lane & 7;
    const int bColSel = ((lane >> 3) & 1) * 16;
    const uint32_t aBase = (uint32_t)((wr * 64 + aRowSel) * ROWB + aColSel);
    const uint32_t bBase = (uint32_t)((wc * 32 + bRowSel) * ROWB + bColSel);

    // loader: per tile, 2 cp.async of 16B per thread (128 rows x 64 B)
    auto ldstage = [&](int c, int s) {
        const long long kofs = (long long)c * 32;
        const uint32_t st = sb + s * STAGE_BYTES;
        const __nv_bfloat16* G[4] = { Ah, Al, Bh, Bl };
        #pragma unroll
        for (int t = 0; t < 4; t++) {
            const int r0 = (t < 2) ? row0 : col0;
            const int ld = (t < 2) ? lda : ldb;
            #pragma unroll
            for (int o = 0; o < 2; o++) {
                const int lin = tid + o * 256;
                const int row = lin >> 2;
                const int cb  = (lin & 3) * 16;
                const char* src = (const char*)G[t] + ((size_t)(r0 + row) * ld + kofs) * 2 + cb;
                cp_async16(st + t * SM_TILE + row * ROWB + cb, src);
            }
        }
        cp_commit();
    };

    float acc[4][4][4];
    #pragma unroll
    for (int i = 0; i < 4; i++)
        #pragma unroll
        for (int j = 0; j < 4; j++)
            #pragma unroll
            for (int r = 0; r < 4; r++) acc[i][j][r] = 0.0f;

    // prologue: fill up to 3 stages
    ldstage(0, 0);
    if (nchunk > 1) ldstage(1, 1); else cp_commit();
    if (nchunk > 2) ldstage(2, 2); else cp_commit();

    for (int c = 0; c < nchunk; c++) {
        if (c + 3 < nchunk) ldstage(c + 3, (c + 3) % NSTAGE);
        else cp_commit();                 // uniform group bookkeeping
        cp_wait<3>();
        __syncthreads();                  // stage c visible

        const uint32_t stg = sb + (c % NSTAGE) * STAGE_BYTES;
        #pragma unroll
        for (int ks = 0; ks < 2; ks++) {
            const uint32_t ko = ks * 32;

            uint32_t ah[4][4], al[4][4], bh[4][2], bl[4][2];
            #pragma unroll
            for (int nt = 0; nt < 4; nt++) {
                const uint32_t off = stg + bBase + nt * (8 * ROWB) + ko;
                ldsm_x2(bh[nt], off + 2 * SM_TILE);
                ldsm_x2(bl[nt], off + 3 * SM_TILE);
            }
            #pragma unroll
            for (int mt = 0; mt < 4; mt++) {
                const uint32_t off = stg + aBase + mt * (16 * ROWB) + ko;
                ldsm_x4(ah[mt], off);
                ldsm_x4(al[mt], off + SM_TILE);
            }

            #pragma unroll
            for (int mt = 0; mt < 4; mt++)
                #pragma unroll
                for (int nt = 0; nt < 4; nt++)
                    mma16816(acc[mt][nt], ah[mt], bh[nt]);
            #pragma unroll
            for (int mt = 0; mt < 4; mt++)
                #pragma unroll
                for (int nt = 0; nt < 4; nt++)
                    mma16816(acc[mt][nt], ah[mt], bl[nt]);
            #pragma unroll
            for (int mt = 0; mt < 4; mt++)
                #pragma unroll
                for (int nt = 0; nt < 4; nt++)
                    mma16816(acc[mt][nt], al[mt], bh[nt]);
        }
        __syncthreads();                  // before buffer reuse
    }

    // epilogue
    #pragma unroll
    for (int mt = 0; mt < 4; mt++) {
        const int r = row0 + wr * 64 + mt * 16 + r4;
        #pragma unroll
        for (int nt = 0; nt < 4; nt++) {
            const int cidx = col0 + wc * 32 + nt * 8 + c4 * 2;
            float b0 = 0.f, b1 = 0.f;
            if (BIAS) { b0 = __ldg(bias + cidx); b1 = __ldg(bias + cidx + 1); }
            const float v00 = alpha * acc[mt][nt][0] + b0;
            const float v01 = alpha * acc[mt][nt][1] + b1;
            const float v10 = alpha * acc[mt][nt][2] + b0;
            const float v11 = alpha * acc[mt][nt][3] + b1;
            if (OUT_SPLIT) {
                __nv_bfloat16 h0, l0, h1, l1;
                split1(v00, h0, l0); split1(v01, h1, l1);
                *(__nv_bfloat162*)(Ch + (size_t)r * N + cidx) = __nv_bfloat162(h0, h1);
                *(__nv_bfloat162*)(Cl + (size_t)r * N + cidx) = __nv_bfloat162(l0, l1);
                split1(v10, h0, l0); split1(v11, h1, l1);
                *(__nv_bfloat162*)(Ch + (size_t)(r + 8) * N + cidx) = __nv_bfloat162(h0, h1);
                *(__nv_bfloat162*)(Cl + (size_t)(r + 8) * N + cidx) = __nv_bfloat162(l0, l1);
            } else {
                float* Cz = C + (size_t)blockIdx.z * sC;
                *(float2*)(Cz + (size_t)r * N + cidx)       = make_float2(v00, v01);
                *(float2*)(Cz + (size_t)(r + 8) * N + cidx) = make_float2(v10, v11);
            }
        }
    }
}

// ---------------------------------------------------------------------------
__global__ void compute_len(const int* __restrict__ mask)
{
    const int b = blockIdx.x;
    const int tid = threadIdx.x;
    __shared__ int red[256];
    int s = 0;
    for (int k = tid; k < SS; k += 256) s += mask[b * SS + k];
    red[tid] = s;
    __syncthreads();
    for (int o = 128; o > 0; o >>= 1) {
        if (tid < o) red[tid] += red[tid + o];
        __syncthreads();
    }
    if (tid == 0) g_len[b] = SS - red[0];
}

__global__ void build_bqk(const float* __restrict__ bq, const float* __restrict__ bk)
{
    const int i = threadIdx.x;
    g_bqk[i] = (i < DKK) ? bq[i] : bk[i - DKK];
}

// ---------------------------------------------------------------------------
__global__ void x_colmean_part(const float* __restrict__ x)
{
    const int d = blockIdx.x * 256 + threadIdx.x;
    const int b = blockIdx.y;
    const int sl = blockIdx.z;
    const float* xb = x + (size_t)b * SS * DD + (size_t)sl * 128 * DD + d;
    float s = 0.0f;
    #pragma unroll 8
    for (int k = 0; k < 128; k++) s += xb[(size_t)k * DD];
    g_xpart[sl][b][d] = s;
}
__global__ void x_colmean_finish()
{
    const int d = blockIdx.x * 256 + threadIdx.x;
    const int b = blockIdx.y;
    float s = 0.0f;
    #pragma unroll
    for (int sl = 0; sl < KSLICE; sl++) s += g_xpart[sl][b][d];
    g_xmean[b * DD + d] = s * (1.0f / (float)SS);
}

// ---------------------------------------------------------------------------
__global__ void vmean_part(const float* __restrict__ Wv)
{
    const int d = blockIdx.x * 256 + threadIdx.x;
    const int sl = blockIdx.y;
    float acc[BB] = {0.f, 0.f, 0.f, 0.f};
    #pragma unroll
    for (int kk = 0; kk < 16; kk++) {
        const int k = sl * 16 + kk;
        const float w = __ldg(Wv + (size_t)k * DD + d);
        #pragma unroll
        for (int b = 0; b < BB; b++) acc[b] += g_xmean[b * DD + k] * w;
    }
    #pragma unroll
    for (int b = 0; b < BB; b++) g_vpart[sl][b][d] = acc[b];
}
__global__ void vmean_finish(const float* __restrict__ bv)
{
    const int d = blockIdx.x * 256 + threadIdx.x;
    const int b = blockIdx.y;
    float s = __ldg(bv + d);
    #pragma unroll
    for (int sl = 0; sl < VSLICE; sl++) s += g_vpart[sl][b][d];
    g_vmean[b * DD + d] = s;
}

// ---------------------------------------------------------------------------
__global__ void split_fp32(const float* __restrict__ src,
                           __nv_bfloat16* __restrict__ hi, __nv_bfloat16* __restrict__ lo,
                           long long n4)
{
    const long long i = (long long)blockIdx.x * blockDim.x + threadIdx.x;
    if (i >= n4) return;
    float4 v = ((const float4*)src)[i];
    __nv_bfloat16 h0, h1, h2, h3, l0, l1, l2, l3;
    split1(v.x, h0, l0); split1(v.y, h1, l1); split1(v.z, h2, l2); split1(v.w, h3, l3);
    __nv_bfloat162* H = (__nv_bfloat162*)hi;
    __nv_bfloat162* L = (__nv_bfloat162*)lo;
    H[2 * i]     = __nv_bfloat162(h0, h1);
    H[2 * i + 1] = __nv_bfloat162(h2, h3);
    L[2 * i]     = __nv_bfloat162(l0, l1);
    L[2 * i + 1] = __nv_bfloat162(l2, l3);
}

// ---------------------------------------------------------------------------
__global__ void transpose_split(const float* __restrict__ in,
                                __nv_bfloat16* __restrict__ oh, __nv_bfloat16* __restrict__ ol,
                                int R, int C, long long sIn, long long sOut, int uselen)
{
    const int c0 = blockIdx.x * 32, r0 = blockIdx.y * 32;
    if (uselen && r0 >= g_len[blockIdx.z]) return;
    __shared__ float t[32][33];
    in += (size_t)blockIdx.z * sIn;
    oh += (size_t)blockIdx.z * sOut;
    ol += (size_t)blockIdx.z * sOut;
    const int tx = threadIdx.x & 31, ty = threadIdx.x >> 5;
    #pragma unroll
    for (int k = 0; k < 32; k += 8)
        t[ty + k][tx] = in[(size_t)(r0 + ty + k) * C + c0 + tx];
    __syncthreads();
    #pragma unroll
    for (int k = 0; k < 32; k += 8) {
        __nv_bfloat16 h, l;
        split1(t[tx][ty + k], h, l);
        oh[(size_t)(c0 + ty + k) * R + r0 + tx] = h;
        ol[(size_t)(c0 + ty + k) * R + r0 + tx] = l;
    }
}

// ---------------------------------------------------------------------------
__global__ void masked_softmax(const int* __restrict__ mask)
{
    const int q = blockIdx.x;
    const int b = blockIdx.y;
    if (mask[b * SS + q] != 0) return;

    const size_t off = ((size_t)b * SS + q) * SS;
    const float* row = g_s + off;
    __nv_bfloat16* ph = g_ph + off;
    __nv_bfloat16* pl = g_pl + off;
    const int tid = threadIdx.x;

    const int L   = g_len[b];
    const int cap = (L + 31) & ~31;

    __shared__ float red[256];

    float vals[8];
    float m = -INFINITY;
    #pragma unroll
    for (int it = 0; it < 8; it++) {
        const int k = tid + it * 256;
        float s = -INFINITY;
        if (k < cap) {
            const bool valid = (k <= q) && (mask[b * SS + k] == 0);
            s = valid ? row[k] : -INFINITY;
        }
        vals[it] = s;
        m = fmaxf(m, s);
    }
    red[tid] = m;
    __syncthreads();
    for (int o = 128; o > 0; o >>= 1) {
        if (tid < o) red[tid] = fmaxf(red[tid], red[tid + o]);
        __syncthreads();
    }
    m = red[0];
    __syncthreads();

    float sum = 0.0f;
    #pragma unroll
    for (int it = 0; it < 8; it++) {
        const float e = (vals[it] == -INFINITY) ? 0.0f : __expf(vals[it] - m);
        vals[it] = e;
        sum += e;
    }
    red[tid] = sum;
    __syncthreads();
    for (int o = 128; o > 0; o >>= 1) {
        if (tid < o) red[tid] += red[tid + o];
        __syncthreads();
    }
    const float inv = 1.0f / red[0];

    #pragma unroll
    for (int it = 0; it < 8; it++) {
        const int k = tid + it * 256;
        if (k < cap) {
            __nv_bfloat16 h, l;
            split1(vals[it] * inv, h, l);
            ph[k] = h;
            pl[k] = l;
        }
    }
}

// ---------------------------------------------------------------------------
__global__ void scatter_padded(const int* __restrict__ mask, float* __restrict__ out)
{
    const int q = blockIdx.x;
    const int b = blockIdx.y;
    if (mask[b * SS + q] == 0) return;
    const int tid = threadIdx.x;
    float* o = out + ((size_t)b * SS + q) * DD;
    const float* vm = g_vmean + b * DD;
    #pragma unroll
    for (int it = 0; it < 4; it++) o[tid + it * 256] = vm[tid + it * 256];
}

// ---------------------------------------------------------------------------
extern "C" void kernel_launch(void* const* d_in, const int* in_sizes, int n_in,
                              void* d_out, int out_size)
{
    const float* x    = (const float*)d_in[0];
    const int*   mask = (const int*)d_in[1];
    const float* Wq   = (const float*)d_in[2];
    const float* bq   = (const float*)d_in[3];
    const float* Wk   = (const float*)d_in[4];
    const float* bk   = (const float*)d_in[5];
    const float* Wv   = (const float*)d_in[6];
    const float* bv   = (const float*)d_in[7];
    float* out = (float*)d_out;

    cudaFuncSetAttribute(gemm_bf16x3<false, false, true, true, 1>,
                         cudaFuncAttributeMaxDynamicSharedMemorySize, SMEM_BYTES);
    cudaFuncSetAttribute(gemm_bf16x3<false, false, true, false, 1>,
                         cudaFuncAttributeMaxDynamicSharedMemorySize, SMEM_BYTES);
    cudaFuncSetAttribute(gemm_bf16x3<true, false, false, false, 2>,
                         cudaFuncAttributeMaxDynamicSharedMemorySize, SMEM_BYTES);
    cudaFuncSetAttribute(gemm_bf16x3<false, true, false, false, 3>,
                         cudaFuncAttributeMaxDynamicSharedMemorySize, SMEM_BYTES);

    __nv_bfloat16 *xh, *xl, *wqkth, *wqktl, *wvth, *wvtl;
    __nv_bfloat16 *qkh, *qkl, *vth, *vtl, *ph, *pl;
    float *v, *s, *bqk;
    cudaGetSymbolAddress((void**)&xh, g_xh);      cudaGetSymbolAddress((void**)&xl, g_xl);
    cudaGetSymbolAddress((void**)&wqkth, g_wqkt_h); cudaGetSymbolAddress((void**)&wqktl, g_wqkt_l);
    cudaGetSymbolAddress((void**)&wvth, g_wvt_h); cudaGetSymbolAddress((void**)&wvtl, g_wvt_l);
    cudaGetSymbolAddress((void**)&qkh, g_qkh);    cudaGetSymbolAddress((void**)&qkl, g_qkl);
    cudaGetSymbolAddress((void**)&v, g_v);
    cudaGetSymbolAddress((void**)&vth, g_vth);    cudaGetSymbolAddress((void**)&vtl, g_vtl);
    cudaGetSymbolAddress((void**)&s, g_s);
    cudaGetSymbolAddress((void**)&ph, g_ph);      cudaGetSymbolAddress((void**)&pl, g_pl);
    cudaGetSymbolAddress((void**)&bqk, g_bqk);

    const float scale = 1.0f / sqrtf((float)DKK);

    // 0. lengths; combined bias; xmean (2-stage); vmean (2-stage)
    compute_len<<<BB, 256>>>(mask);
    build_bqk<<<1, 2 * DKK>>>(bq, bk);
    x_colmean_part<<<dim3(DD / 256, BB, KSLICE), 256>>>(x);
    x_colmean_finish<<<dim3(DD / 256, BB), 256>>>();
    vmean_part<<<dim3(DD / 256, VSLICE), 256>>>(Wv);
    vmean_finish<<<dim3(DD / 256, BB), 256>>>(bv);

    // 1. split x into bf16 hi/lo
    {
        long long n4 = (long long)MTOT * DD / 4;
        split_fp32<<<(unsigned)((n4 + 255) / 256), 256>>>(x, xh, xl, n4);
    }
    // 2. transpose + split weights.  Wq -> rows 0..127 of WqkT, Wk -> 128..255
    transpose_split<<<dim3(DKK / 32, DD / 32, 1), 256>>>(Wq, wqkth, wqktl, DD, DKK, 0, 0, 0);
    transpose_split<<<dim3(DKK / 32, DD / 32, 1), 256>>>(Wk, wqkth + (size_t)DKK * DD,
                                                         wqktl + (size_t)DKK * DD, DD, DKK, 0, 0, 0);
    transpose_split<<<dim3(DD / 32, DD / 32, 1), 256>>>(Wv, wvth, wvtl, DD, DD, 0, 0, 0);

    // 3a. fused q|k projection: [8192, 256] = x @ [Wq|Wk]
    gemm_bf16x3<false, false, true, true, 1><<<dim3(2 * DKK / 128, MTOT / 128, 1), NTHR, SMEM_BYTES>>>(
        xh, xl, wqkth, wqktl, bqk, nullptr, qkh, qkl,
        MTOT, 2 * DKK, DD, DD, DD, 0, 0, 0, 1.0f);
    // 3b. v projection
    gemm_bf16x3<false, false, true, false, 1><<<dim3(DD / 128, MTOT / 128, 1), NTHR, SMEM_BYTES>>>(
        xh, xl, wvth, wvtl, bv, v, nullptr, nullptr,
        MTOT, DD, DD, DD, DD, 0, 0, 0, 1.0f);

    // 4. transpose+split v per batch (skip rows >= len)
    transpose_split<<<dim3(DD / 32, SS / 32, BB), 256>>>(
        v, vth, vtl, SS, DD, (long long)SS * DD, (long long)SS * DD, 1);

    // 5. scores = q @ k^T from the combined buffer, lower-triangle clipped
    gemm_bf16x3<true, false, false, false, 2><<<dim3(SS / 128, SS / 128, BB), NTHR, SMEM_BYTES>>>(
        qkh, qkl, qkh + DKK, qkl + DKK, nullptr, s, nullptr, nullptr,
        SS, SS, DKK, 2 * DKK, 2 * DKK,
        (long long)SS * 2 * DKK, (long long)SS * 2 * DKK, (long long)SS * SS, scale);

    // 6. masked softmax -> P (bf16 hi/lo), bounded to round_up(len,32)
    masked_softmax<<<dim3(SS, BB), 256>>>(mask);

    // 7. out = P @ V^T-layout, K truncated to min(causal, len); skip rows>=len
    gemm_bf16x3<false, true, false, false, 3><<<dim3(DD / 128, SS / 128, BB), NTHR, SMEM_BYTES>>>(
        ph, pl, vth, vtl, nullptr, out, nullptr, nullptr,
        SS, DD, SS, SS, SS,
        (long long)SS * SS, (long long)DD * SS, (long long)SS * DD, 1.0f);

    // 8. padded rows <- uniform attention
    scatter_padded<<<dim3(SS, BB), 256>>>(mask, out);
}

// round 16
// speedup vs baseline: 1.1008x; 1.0607x over previous
#include <cuda_runtime.h>
#include <cuda_bf16.h>
#include <math.h>
#include <stdint.h>

#define BB 4
#define SS 2048
#define DD 1024
#define DKK 128
#define MTOT (BB * SS)   // 8192
#define KSLICE 16
#define VSLICE 64

// ---------------------------------------------------------------------------
// Device scratch (allocation-free per harness rules)
// ---------------------------------------------------------------------------
__device__ __nv_bfloat16 g_xh[(size_t)MTOT * DD];
__device__ __nv_bfloat16 g_xl[(size_t)MTOT * DD];
__device__ __nv_bfloat16 g_wqkt_h[2 * DKK * DD], g_wqkt_l[2 * DKK * DD]; // [256,1024]
__device__ __nv_bfloat16 g_wvt_h[DD * DD],  g_wvt_l[DD * DD];
__device__ float g_bqk[2 * DKK];
__device__ __nv_bfloat16 g_qkh[(size_t)MTOT * 2 * DKK], g_qkl[(size_t)MTOT * 2 * DKK];
__device__ __nv_bfloat16 g_vth[(size_t)BB * DD * SS], g_vtl[(size_t)BB * DD * SS];
__device__ float g_s[(size_t)BB * SS * SS];
__device__ __nv_bfloat16 g_ph[(size_t)BB * SS * SS], g_pl[(size_t)BB * SS * SS];
__device__ float g_xpart[KSLICE][BB][DD];
__device__ float g_vpart[VSLICE][BB][DD];
__device__ float g_xmean[BB * DD];
__device__ float g_vmean[BB * DD];
__device__ int   g_len[BB];

// ---------------------------------------------------------------------------
// mma.sync + cp.async + ldmatrix helpers (plain compute_103-safe PTX)
// ---------------------------------------------------------------------------
__device__ __forceinline__ uint32_t smem_u32(const void* p) {
    uint32_t a;
    asm("{ .reg .u64 t; cvta.to.shared.u64 t, %1; cvt.u32.u64 %0, t; }"
        : "=r"(a) : "l"(p));
    return a;
}
__device__ __forceinline__ void cp_async16(uint32_t dst, const void* src) {
    asm volatile("cp.async.cg.shared.global [%0], [%1], 16;"
                 :: "r"(dst), "l"(src) : "memory");
}
__device__ __forceinline__ void cp_commit() {
    asm volatile("cp.async.commit_group;" ::: "memory");
}
template<int N>
__device__ __forceinline__ void cp_wait() {
    asm volatile("cp.async.wait_group %0;" :: "n"(N) : "memory");
}
__device__ __forceinline__ void mma16816(float* c, const uint32_t* a, const uint32_t* b) {
    asm volatile(
        "mma.sync.aligned.m16n8k16.row.col.f32.bf16.bf16.f32 "
        "{%0,%1,%2,%3}, {%4,%5,%6,%7}, {%8,%9}, {%0,%1,%2,%3};"
        : "+f"(c[0]), "+f"(c[1]), "+f"(c[2]), "+f"(c[3])
        : "r"(a[0]), "r"(a[1]), "r"(a[2]), "r"(a[3]), "r"(b[0]), "r"(b[1]));
}
__device__ __forceinline__ void ldsm_x4(uint32_t* r, uint32_t addr) {
    asm volatile("ldmatrix.sync.aligned.m8n8.x4.shared.b16 {%0,%1,%2,%3}, [%4];"
                 : "=r"(r[0]), "=r"(r[1]), "=r"(r[2]), "=r"(r[3]) : "r"(addr));
}
__device__ __forceinline__ void ldsm_x2(uint32_t* r, uint32_t addr) {
    asm volatile("ldmatrix.sync.aligned.m8n8.x2.shared.b16 {%0,%1}, [%2];"
                 : "=r"(r[0]), "=r"(r[1]) : "r"(addr));
}

__device__ __forceinline__ void split1(float x, __nv_bfloat16& h, __nv_bfloat16& l) {
    h = __float2bfloat16(x);
    l = __float2bfloat16(x - __bfloat162float(h));
}

// ---------------------------------------------------------------------------
// bf16x3 GEMM on HMMA — R11 geometry (256 thr, 2x4 warps, 64x32 warp tile),
// 4-stage cp.async pipeline (prefetch-before-compute, cp_wait<3>).
// C[M,N] = alpha*(A @ B^T) (+ bias);  A bf16 (hi,lo) [M,*] row-stride lda,
// B bf16 (hi,lo) [N,*] row-stride ldb; K = reduction depth.
// LENMODE: 0 none; 1 proj (skip (row0%2048)>=len); 2 scores; 3 P.V (+ y-flip
//          so longest-K tiles launch first).
// OUTMODE: 0 fp32 C; 1 bf16 hi/lo split (row-major);
//          2 bf16 hi/lo split TRANSPOSED per batch -> Ch/Cl are [B][D][S]
//            (v-projection path; SMEM-staged tile transpose in the epilogue)
// ---------------------------------------------------------------------------
#define ROWB 80
#define SM_TILE (128 * ROWB)            // 10240
#define STAGE_BYTES (4 * SM_TILE)       // 40960: Ah, Al, Bh, Bl
#define NSTAGE 4
#define SMEM_BYTES (NSTAGE * STAGE_BYTES)  // 163840
#define NTHR 256
#define TPAD 272                        // transpose-stage row stride (bytes)

template<bool SKIP_UPPER, bool CAUSAL_K, bool BIAS, int OUTMODE, int LENMODE>
__global__ void __launch_bounds__(NTHR, 1)
gemm_bf16x3(const __nv_bfloat16* __restrict__ Ah, const __nv_bfloat16* __restrict__ Al,
            const __nv_bfloat16* __restrict__ Bh, const __nv_bfloat16* __restrict__ Bl,
            const float* __restrict__ bias, float* __restrict__ C,
            __nv_bfloat16* __restrict__ Ch, __nv_bfloat16* __restrict__ Cl,
            int M, int N, int K, int lda, int ldb,
            long long sA, long long sB, long long sC, float alpha)
{
    if (SKIP_UPPER && blockIdx.x > blockIdx.y) return;

    int by = blockIdx.y;
    if (LENMODE == 3) by = gridDim.y - 1 - blockIdx.y;   // longest-K first

    const int row0 = by * 128;
    const int col0 = blockIdx.x * 128;

    int Keff = K;
    if (CAUSAL_K) { const int kl = (by + 1) * 128; Keff = kl < K ? kl : K; }

    if (LENMODE == 1) {
        const int b = row0 >> 11;
        if ((row0 & 2047) >= g_len[b]) return;
    } else if (LENMODE == 2) {
        const int L = g_len[blockIdx.z];
        if (row0 >= L || col0 >= L) return;
    } else if (LENMODE == 3) {
        const int L = g_len[blockIdx.z];
        if (row0 >= L) return;
        const int kcap = (L + 31) & ~31;
        if (kcap < Keff) Keff = kcap;
    }
    const int nchunk = Keff >> 5;   // K-chunk = 32

    extern __shared__ char smem[];

    const int tid = threadIdx.x;
    const int wid = tid >> 5, lane = tid & 31;
    const int wr = wid >> 2;        // 0..1  warp row (64 rows)
    const int wc = wid & 3;         // 0..3  warp col (32 cols)
    const int r4 = lane >> 2;
    const int c4 = lane & 3;

    Ah += (size_t)blockIdx.z * sA;  Al += (size_t)blockIdx.z * sA;
    Bh += (size_t)blockIdx.z * sB;  Bl += (size_t)blockIdx.z * sB;

    const uint32_t sb = smem_u32(smem);

    const int aRowSel = ((lane >> 3) & 1) * 8 + (lane & 7);
    const int aColSel = (lane >> 4) * 16;
    const int bRowSel = lane & 7;
    const int bColSel = ((lane >> 3) & 1) * 16;
    const uint32_t aBase = (uint32_t)((wr * 64 + aRowSel) * ROWB + aColSel);
    const uint32_t bBase = (uint32_t)((wc * 32 + bRowSel) * ROWB + bColSel);

    // loader: per tile, 2 cp.async of 16B per thread (128 rows x 64 B)
    auto ldstage = [&](int c, int s) {
        const long long kofs = (long long)c * 32;
        const uint32_t st = sb + s * STAGE_BYTES;
        const __nv_bfloat16* G[4] = { Ah, Al, Bh, Bl };
        #pragma unroll
        for (int t = 0; t < 4; t++) {
            const int r0 = (t < 2) ? row0 : col0;
            const int ld = (t < 2) ? lda : ldb;
            #pragma unroll
            for (int o = 0; o < 2; o++) {
                const int lin = tid + o * 256;
                const int row = lin >> 2;
                const int cb  = (lin & 3) * 16;
                const char* src = (const char*)G[t] + ((size_t)(r0 + row) * ld + kofs) * 2 + cb;
                cp_async16(st + t * SM_TILE + row * ROWB + cb, src);
            }
        }
        cp_commit();
    };

    float acc[4][4][4];
    #pragma unroll
    for (int i = 0; i < 4; i++)
        #pragma unroll
        for (int j = 0; j < 4; j++)
            #pragma unroll
            for (int r = 0; r < 4; r++) acc[i][j][r] = 0.0f;

    // prologue: fill up to 3 stages
    ldstage(0, 0);
    if (nchunk > 1) ldstage(1, 1); else cp_commit();
    if (nchunk > 2) ldstage(2, 2); else cp_commit();

    for (int c = 0; c < nchunk; c++) {
        if (c + 3 < nchunk) ldstage(c + 3, (c + 3) % NSTAGE);
        else cp_commit();                 // uniform group bookkeeping
        cp_wait<3>();
        __syncthreads();                  // stage c visible

        const uint32_t stg = sb + (c % NSTAGE) * STAGE_BYTES;
        #pragma unroll
        for (int ks = 0; ks < 2; ks++) {
            const uint32_t ko = ks * 32;

            uint32_t ah[4][4], al[4][4], bh[4][2], bl[4][2];
            #pragma unroll
            for (int nt = 0; nt < 4; nt++) {
                const uint32_t off = stg + bBase + nt * (8 * ROWB) + ko;
                ldsm_x2(bh[nt], off + 2 * SM_TILE);
                ldsm_x2(bl[nt], off + 3 * SM_TILE);
            }
            #pragma unroll
            for (int mt = 0; mt < 4; mt++) {
                const uint32_t off = stg + aBase + mt * (16 * ROWB) + ko;
                ldsm_x4(ah[mt], off);
                ldsm_x4(al[mt], off + SM_TILE);
            }

            #pragma unroll
            for (int mt = 0; mt < 4; mt++)
                #pragma unroll
                for (int nt = 0; nt < 4; nt++)
                    mma16816(acc[mt][nt], ah[mt], bh[nt]);
            #pragma unroll
            for (int mt = 0; mt < 4; mt++)
                #pragma unroll
                for (int nt = 0; nt < 4; nt++)
                    mma16816(acc[mt][nt], ah[mt], bl[nt]);
            #pragma unroll
            for (int mt = 0; mt < 4; mt++)
                #pragma unroll
                for (int nt = 0; nt < 4; nt++)
                    mma16816(acc[mt][nt], al[mt], bh[nt]);
        }
        __syncthreads();                  // before buffer reuse
    }

    // ---------------- epilogue ----------------
    if (OUTMODE == 2) {
        // Transposed bf16 hi/lo output via SMEM staging (mainloop SMEM free
        // after the final __syncthreads above).
        #pragma unroll
        for (int mt = 0; mt < 4; mt++) {
            const int rl = wr * 64 + mt * 16 + r4;
            #pragma unroll
            for (int nt = 0; nt < 4; nt++) {
                const int cl = wc * 32 + nt * 8 + c4 * 2;
                const int cidx = col0 + cl;
                float b0 = 0.f, b1 = 0.f;
                if (BIAS) { b0 = __ldg(bias + cidx); b1 = __ldg(bias + cidx + 1); }
                const float v00 = alpha * acc[mt][nt][0] + b0;
                const float v01 = alpha * acc[mt][nt][1] + b1;
                const float v10 = alpha * acc[mt][nt][2] + b0;
                const float v11 = alpha * acc[mt][nt][3] + b1;
                __nv_bfloat16 h, l;
                split1(v00, h, l);
                *(__nv_bfloat16*)(smem + cl * TPAD + rl * 2) = h;
                *(__nv_bfloat16*)(smem + 128 * TPAD + cl * TPAD + rl * 2) = l;
                split1(v01, h, l);
                *(__nv_bfloat16*)(smem + (cl + 1) * TPAD + rl * 2) = h;
                *(__nv_bfloat16*)(smem + 128 * TPAD + (cl + 1) * TPAD + rl * 2) = l;
                split1(v10, h, l);
                *(__nv_bfloat16*)(smem + cl * TPAD + (rl + 8) * 2) = h;
                *(__nv_bfloat16*)(smem + 128 * TPAD + cl * TPAD + (rl + 8) * 2) = l;
                split1(v11, h, l);
                *(__nv_bfloat16*)(smem + (cl + 1) * TPAD + (rl + 8) * 2) = h;
                *(__nv_bfloat16*)(smem + 128 * TPAD + (cl + 1) * TPAD + (rl + 8) * 2) = l;
            }
        }
        __syncthreads();
        // coalesced write-out: thread -> (d-row, half); each half = 64 elems
        // = 128 bytes = 8 x uint4 per thread.
        const int bidx = row0 >> 11;           // batch
        const int sloc = row0 & 2047;          // s offset within batch
        const int dl = tid >> 1;
        const int hf = tid & 1;
        __nv_bfloat16* oh = Ch + (size_t)bidx * DD * SS + (size_t)(col0 + dl) * SS + sloc + hf * 64;
        __nv_bfloat16* ol = Cl + (size_t)bidx * DD * SS + (size_t)(col0 + dl) * SS + sloc + hf * 64;
        const char* sh = smem + dl * TPAD + hf * 128;
        const char* sl = smem + 128 * TPAD + dl * TPAD + hf * 128;
        #pragma unroll
        for (int i = 0; i < 8; i++) {
            ((uint4*)oh)[i] = *(const uint4*)(sh + i * 16);
            ((uint4*)ol)[i] = *(const uint4*)(sl + i * 16);
        }
        return;
    }

    #pragma unroll
    for (int mt = 0; mt < 4; mt++) {
        const int r = row0 + wr * 64 + mt * 16 + r4;
        #pragma unroll
        for (int nt = 0; nt < 4; nt++) {
            const int cidx = col0 + wc * 32 + nt * 8 + c4 * 2;
            float b0 = 0.f, b1 = 0.f;
            if (BIAS) { b0 = __ldg(bias + cidx); b1 = __ldg(bias + cidx + 1); }
            const float v00 = alpha * acc[mt][nt][0] + b0;
            const float v01 = alpha * acc[mt][nt][1] + b1;
            const float v10 = alpha * acc[mt][nt][2] + b0;
            const float v11 = alpha * acc[mt][nt][3] + b1;
            if (OUTMODE == 1) {
                __nv_bfloat16 h0, l0, h1, l1;
                split1(v00, h0, l0); split1(v01, h1, l1);
                *(__nv_bfloat162*)(Ch + (size_t)r * N + cidx) = __nv_bfloat162(h0, h1);
                *(__nv_bfloat162*)(Cl + (size_t)r * N + cidx) = __nv_bfloat162(l0, l1);
                split1(v10, h0, l0); split1(v11, h1, l1);
                *(__nv_bfloat162*)(Ch + (size_t)(r + 8) * N + cidx) = __nv_bfloat162(h0, h1);
                *(__nv_bfloat162*)(Cl + (size_t)(r + 8) * N + cidx) = __nv_bfloat162(l0, l1);
            } else {
                float* Cz = C + (size_t)blockIdx.z * sC;
                *(float2*)(Cz + (size_t)r * N + cidx)       = make_float2(v00, v01);
                *(float2*)(Cz + (size_t)(r + 8) * N + cidx) = make_float2(v10, v11);
            }
        }
    }
}

// ---------------------------------------------------------------------------
// prep: per-batch lengths (block b) + combined bias (block 0)
// ---------------------------------------------------------------------------
__global__ void prep(const int* __restrict__ mask,
                     const float* __restrict__ bq, const float* __restrict__ bk)
{
    const int b = blockIdx.x;
    const int tid = threadIdx.x;
    if (b == 0) g_bqk[tid] = (tid < DKK) ? bq[tid] : bk[tid - DKK];
    __shared__ int red[256];
    int s = 0;
    for (int k = tid; k < SS; k += 256) s += mask[b * SS + k];
    red[tid] = s;
    __syncthreads();
    for (int o = 128; o > 0; o >>= 1) {
        if (tid < o) red[tid] += red[tid + o];
        __syncthreads();
    }
    if (tid == 0) g_len[b] = SS - red[0];
}

// ---------------------------------------------------------------------------
__global__ void x_colmean_part(const float* __restrict__ x)
{
    const int d = blockIdx.x * 256 + threadIdx.x;
    const int b = blockIdx.y;
    const int sl = blockIdx.z;
    const float* xb = x + (size_t)b * SS * DD + (size_t)sl * 128 * DD + d;
    float s = 0.0f;
    #pragma unroll 8
    for (int k = 0; k < 128; k++) s += xb[(size_t)k * DD];
    g_xpart[sl][b][d] = s;
}
__global__ void x_colmean_finish()
{
    const int d = blockIdx.x * 256 + threadIdx.x;
    const int b = blockIdx.y;
    float s = 0.0f;
    #pragma unroll
    for (int sl = 0; sl < KSLICE; sl++) s += g_xpart[sl][b][d];
    g_xmean[b * DD + d] = s * (1.0f / (float)SS);
}

// ---------------------------------------------------------------------------
__global__ void vmean_part(const float* __restrict__ Wv)
{
    const int d = blockIdx.x * 256 + threadIdx.x;
    const int sl = blockIdx.y;
    float acc[BB] = {0.f, 0.f, 0.f, 0.f};
    #pragma unroll
    for (int kk = 0; kk < 16; kk++) {
        const int k = sl * 16 + kk;
        const float w = __ldg(Wv + (size_t)k * DD + d);
        #pragma unroll
        for (int b = 0; b < BB; b++) acc[b] += g_xmean[b * DD + k] * w;
    }
    #pragma unroll
    for (int b = 0; b < BB; b++) g_vpart[sl][b][d] = acc[b];
}
__global__ void vmean_finish(const float* __restrict__ bv)
{
    const int d = blockIdx.x * 256 + threadIdx.x;
    const int b = blockIdx.y;
    float s = __ldg(bv + d);
    #pragma unroll
    for (int sl = 0; sl < VSLICE; sl++) s += g_vpart[sl][b][d];
    g_vmean[b * DD + d] = s;
}

// ---------------------------------------------------------------------------
__global__ void split_fp32(const float* __restrict__ src,
                           __nv_bfloat16* __restrict__ hi, __nv_bfloat16* __restrict__ lo,
                           long long n4)
{
    const long long i = (long long)blockIdx.x * blockDim.x + threadIdx.x;
    if (i >= n4) return;
    float4 v = ((const float4*)src)[i];
    __nv_bfloat16 h0, h1, h2, h3, l0, l1, l2, l3;
    split1(v.x, h0, l0); split1(v.y, h1, l1); split1(v.z, h2, l2); split1(v.w, h3, l3);
    __nv_bfloat162* H = (__nv_bfloat162*)hi;
    __nv_bfloat162* L = (__nv_bfloat162*)lo;
    H[2 * i]     = __nv_bfloat162(h0, h1);
    H[2 * i + 1] = __nv_bfloat162(h2, h3);
    L[2 * i]     = __nv_bfloat162(l0, l1);
    L[2 * i + 1] = __nv_bfloat162(l2, l3);
}

// ---------------------------------------------------------------------------
// fp32 [R,C] -> transposed bf16 hi/lo [C,R]; used for weights only now.
// ---------------------------------------------------------------------------
__global__ void transpose_split(const float* __restrict__ in,
                                __nv_bfloat16* __restrict__ oh, __nv_bfloat16* __restrict__ ol,
                                int R, int C)
{
    const int c0 = blockIdx.x * 32, r0 = blockIdx.y * 32;
    __shared__ float t[32][33];
    const int tx = threadIdx.x & 31, ty = threadIdx.x >> 5;
    #pragma unroll
    for (int k = 0; k < 32; k += 8)
        t[ty + k][tx] = in[(size_t)(r0 + ty + k) * C + c0 + tx];
    __syncthreads();
    #pragma unroll
    for (int k = 0; k < 32; k += 8) {
        __nv_bfloat16 h, l;
        split1(t[tx][ty + k], h, l);
        oh[(size_t)(c0 + ty + k) * R + r0 + tx] = h;
        ol[(size_t)(c0 + ty + k) * R + r0 + tx] = l;
    }
}

// ---------------------------------------------------------------------------
__global__ void masked_softmax(const int* __restrict__ mask)
{
    const int q = blockIdx.x;
    const int b = blockIdx.y;
    if (mask[b * SS + q] != 0) return;

    const size_t off = ((size_t)b * SS + q) * SS;
    const float* row = g_s + off;
    __nv_bfloat16* ph = g_ph + off;
    __nv_bfloat16* pl = g_pl + off;
    const int tid = threadIdx.x;

    const int L   = g_len[b];
    const int cap = (L + 31) & ~31;

    __shared__ float red[256];

    float vals[8];
    float m = -INFINITY;
    #pragma unroll
    for (int it = 0; it < 8; it++) {
        const int k = tid + it * 256;
        float s = -INFINITY;
        if (k < cap) {
            const bool valid = (k <= q) && (mask[b * SS + k] == 0);
            s = valid ? row[k] : -INFINITY;
        }
        vals[it] = s;
        m = fmaxf(m, s);
    }
    red[tid] = m;
    __syncthreads();
    for (int o = 128; o > 0; o >>= 1) {
        if (tid < o) red[tid] = fmaxf(red[tid], red[tid + o]);
        __syncthreads();
    }
    m = red[0];
    __syncthreads();

    float sum = 0.0f;
    #pragma unroll
    for (int it = 0; it < 8; it++) {
        const float e = (vals[it] == -INFINITY) ? 0.0f : __expf(vals[it] - m);
        vals[it] = e;
        sum += e;
    }
    red[tid] = sum;
    __syncthreads();
    for (int o = 128; o > 0; o >>= 1) {
        if (tid < o) red[tid] += red[tid + o];
        __syncthreads();
    }
    const float inv = 1.0f / red[0];

    #pragma unroll
    for (int it = 0; it < 8; it++) {
        const int k = tid + it * 256;
        if (k < cap) {
            __nv_bfloat16 h, l;
            split1(vals[it] * inv, h, l);
            ph[k] = h;
            pl[k] = l;
        }
    }
}

// ---------------------------------------------------------------------------
__global__ void scatter_padded(const int* __restrict__ mask, float* __restrict__ out)
{
    const int q = blockIdx.x;
    const int b = blockIdx.y;
    if (mask[b * SS + q] == 0) return;
    const int tid = threadIdx.x;
    float* o = out + ((size_t)b * SS + q) * DD;
    const float* vm = g_vmean + b * DD;
    #pragma unroll
    for (int it = 0; it < 4; it++) o[tid + it * 256] = vm[tid + it * 256];
}

// ---------------------------------------------------------------------------
extern "C" void kernel_launch(void* const* d_in, const int* in_sizes, int n_in,
                              void* d_out, int out_size)
{
    const float* x    = (const float*)d_in[0];
    const int*   mask = (const int*)d_in[1];
    const float* Wq   = (const float*)d_in[2];
    const float* bq   = (const float*)d_in[3];
    const float* Wk   = (const float*)d_in[4];
    const float* bk   = (const float*)d_in[5];
    const float* Wv   = (const float*)d_in[6];
    const float* bv   = (const float*)d_in[7];
    float* out = (float*)d_out;

    cudaFuncSetAttribute(gemm_bf16x3<false, false, true, 1, 1>,
                         cudaFuncAttributeMaxDynamicSharedMemorySize, SMEM_BYTES);
    cudaFuncSetAttribute(gemm_bf16x3<false, false, true, 2, 1>,
                         cudaFuncAttributeMaxDynamicSharedMemorySize, SMEM_BYTES);
    cudaFuncSetAttribute(gemm_bf16x3<true, false, false, 0, 2>,
                         cudaFuncAttributeMaxDynamicSharedMemorySize, SMEM_BYTES);
    cudaFuncSetAttribute(gemm_bf16x3<false, true, false, 0, 3>,
                         cudaFuncAttributeMaxDynamicSharedMemorySize, SMEM_BYTES);

    __nv_bfloat16 *xh, *xl, *wqkth, *wqktl, *wvth, *wvtl;
    __nv_bfloat16 *qkh, *qkl, *vth, *vtl, *ph, *pl;
    float *s, *bqk;
    cudaGetSymbolAddress((void**)&xh, g_xh);      cudaGetSymbolAddress((void**)&xl, g_xl);
    cudaGetSymbolAddress((void**)&wqkth, g_wqkt_h); cudaGetSymbolAddress((void**)&wqktl, g_wqkt_l);
    cudaGetSymbolAddress((void**)&wvth, g_wvt_h); cudaGetSymbolAddress((void**)&wvtl, g_wvt_l);
    cudaGetSymbolAddress((void**)&qkh, g_qkh);    cudaGetSymbolAddress((void**)&qkl, g_qkl);
    cudaGetSymbolAddress((void**)&vth, g_vth);    cudaGetSymbolAddress((void**)&vtl, g_vtl);
    cudaGetSymbolAddress((void**)&s, g_s);
    cudaGetSymbolAddress((void**)&ph, g_ph);      cudaGetSymbolAddress((void**)&pl, g_pl);
    cudaGetSymbolAddress((void**)&bqk, g_bqk);

    const float scale = 1.0f / sqrtf((float)DKK);

    // 0. lengths + combined bias; xmean (2-stage); vmean (2-stage)
    prep<<<BB, 256>>>(mask, bq, bk);
    x_colmean_part<<<dim3(DD / 256, BB, KSLICE), 256>>>(x);
    x_colmean_finish<<<dim3(DD / 256, BB), 256>>>();
    vmean_part<<<dim3(DD / 256, VSLICE), 256>>>(Wv);
    vmean_finish<<<dim3(DD / 256, BB), 256>>>(bv);

    // 1. split x into bf16 hi/lo
    {
        long long n4 = (long long)MTOT * DD / 4;
        split_fp32<<<(unsigned)((n4 + 255) / 256), 256>>>(x, xh, xl, n4);
    }
    // 2. transpose + split weights.  Wq -> rows 0..127 of WqkT, Wk -> 128..255
    transpose_split<<<dim3(DKK / 32, DD / 32, 1), 256>>>(Wq, wqkth, wqktl, DD, DKK);
    transpose_split<<<dim3(DKK / 32, DD / 32, 1), 256>>>(Wk, wqkth + (size_t)DKK * DD,
                                                         wqktl + (size_t)DKK * DD, DD, DKK);
    transpose_split<<<dim3(DD / 32, DD / 32, 1), 256>>>(Wv, wvth, wvtl, DD, DD);

    // 3a. fused q|k projection: [8192, 256] = x @ [Wq|Wk]
    gemm_bf16x3<false, false, true, 1, 1><<<dim3(2 * DKK / 128, MTOT / 128, 1), NTHR, SMEM_BYTES>>>(
        xh, xl, wqkth, wqktl, bqk, nullptr, qkh, qkl,
        MTOT, 2 * DKK, DD, DD, DD, 0, 0, 0, 1.0f);
    // 3b. v projection -> TRANSPOSED bf16 hi/lo [B][D][S] directly
    gemm_bf16x3<false, false, true, 2, 1><<<dim3(DD / 128, MTOT / 128, 1), NTHR, SMEM_BYTES>>>(
        xh, xl, wvth, wvtl, bv, nullptr, vth, vtl,
        MTOT, DD, DD, DD, DD, 0, 0, 0, 1.0f);

    // 4. scores = q @ k^T from the combined buffer, lower-triangle clipped
    gemm_bf16x3<true, false, false, 0, 2><<<dim3(SS / 128, SS / 128, BB), NTHR, SMEM_BYTES>>>(
        qkh, qkl, qkh + DKK, qkl + DKK, nullptr, s, nullptr, nullptr,
        SS, SS, DKK, 2 * DKK, 2 * DKK,
        (long long)SS * 2 * DKK, (long long)SS * 2 * DKK, (long long)SS * SS, scale);

    // 5. masked softmax -> P (bf16 hi/lo), bounded to round_up(len,32)
    masked_softmax<<<dim3(SS, BB), 256>>>(mask);

    // 6. out = P @ V^T-layout, K truncated to min(causal, len); skip rows>=len;
    //    longest-K tiles launch first
    gemm_bf16x3<false, true, false, 0, 3><<<dim3(DD / 128, SS / 128, BB), NTHR, SMEM_BYTES>>>(
        ph, pl, vth, vtl, nullptr, out, nullptr, nullptr,
        SS, DD, SS, SS, SS,
        (long long)SS * SS, (long long)DD * SS, (long long)SS * DD, 1.0f);

    // 7. padded rows <- uniform attention
    scatter_padded<<<dim3(SS, BB), 256>>>(mask, out);
}

// round 17
// speedup vs baseline: 1.1024x; 1.0015x over previous
#include <cuda_runtime.h>
#include <cuda_bf16.h>
#include <math.h>
#include <stdint.h>

#define BB 4
#define SS 2048
#define DD 1024
#define DKK 128
#define MTOT (BB * SS)   // 8192
#define KSLICE 16
#define VSLICE 64

// ---------------------------------------------------------------------------
// Device scratch (allocation-free per harness rules)
// ---------------------------------------------------------------------------
__device__ __nv_bfloat16 g_xh[(size_t)MTOT * DD];
__device__ __nv_bfloat16 g_xl[(size_t)MTOT * DD];
__device__ __nv_bfloat16 g_wqkt_h[2 * DKK * DD], g_wqkt_l[2 * DKK * DD]; // [256,1024]
__device__ __nv_bfloat16 g_wvt_h[DD * DD],  g_wvt_l[DD * DD];
__device__ float g_bqk[2 * DKK];
__device__ __nv_bfloat16 g_qkh[(size_t)MTOT * 2 * DKK], g_qkl[(size_t)MTOT * 2 * DKK];
__device__ __nv_bfloat16 g_vth[(size_t)BB * DD * SS], g_vtl[(size_t)BB * DD * SS];
__device__ float g_s[(size_t)BB * SS * SS];
__device__ __nv_bfloat16 g_ph[(size_t)BB * SS * SS], g_pl[(size_t)BB * SS * SS];
__device__ float g_xpart[KSLICE][BB][DD];
__device__ float g_vpart[VSLICE][BB][DD];
__device__ float g_xmean[BB * DD];
__device__ float g_vmean[BB * DD];
__device__ int   g_len[BB];

// ---------------------------------------------------------------------------
// mma.sync + cp.async + ldmatrix helpers (plain compute_103-safe PTX)
// ---------------------------------------------------------------------------
__device__ __forceinline__ uint32_t smem_u32(const void* p) {
    uint32_t a;
    asm("{ .reg .u64 t; cvta.to.shared.u64 t, %1; cvt.u32.u64 %0, t; }"
        : "=r"(a) : "l"(p));
    return a;
}
__device__ __forceinline__ void cp_async16(uint32_t dst, const void* src) {
    asm volatile("cp.async.cg.shared.global [%0], [%1], 16;"
                 :: "r"(dst), "l"(src) : "memory");
}
__device__ __forceinline__ void cp_commit() {
    asm volatile("cp.async.commit_group;" ::: "memory");
}
template<int N>
__device__ __forceinline__ void cp_wait() {
    asm volatile("cp.async.wait_group %0;" :: "n"(N) : "memory");
}
__device__ __forceinline__ void mma16816(float* c, const uint32_t* a, const uint32_t* b) {
    asm volatile(
        "mma.sync.aligned.m16n8k16.row.col.f32.bf16.bf16.f32 "
        "{%0,%1,%2,%3}, {%4,%5,%6,%7}, {%8,%9}, {%0,%1,%2,%3};"
        : "+f"(c[0]), "+f"(c[1]), "+f"(c[2]), "+f"(c[3])
        : "r"(a[0]), "r"(a[1]), "r"(a[2]), "r"(a[3]), "r"(b[0]), "r"(b[1]));
}
__device__ __forceinline__ void ldsm_x4(uint32_t* r, uint32_t addr) {
    asm volatile("ldmatrix.sync.aligned.m8n8.x4.shared.b16 {%0,%1,%2,%3}, [%4];"
                 : "=r"(r[0]), "=r"(r[1]), "=r"(r[2]), "=r"(r[3]) : "r"(addr));
}
__device__ __forceinline__ void ldsm_x2(uint32_t* r, uint32_t addr) {
    asm volatile("ldmatrix.sync.aligned.m8n8.x2.shared.b16 {%0,%1}, [%2];"
                 : "=r"(r[0]), "=r"(r[1]) : "r"(addr));
}

__device__ __forceinline__ void split1(float x, __nv_bfloat16& h, __nv_bfloat16& l) {
    h = __float2bfloat16(x);
    l = __float2bfloat16(x - __bfloat162float(h));
}

// ---------------------------------------------------------------------------
// bf16x3 GEMM on HMMA — R11 geometry (256 thr, 2x4 warps, 64x32 warp tile),
// 4-stage cp.async pipeline (prefetch-before-compute, cp_wait<3>).
// C[M,N] = alpha*(A @ B^T) (+ bias);  A bf16 (hi,lo) [M,*] row-stride lda,
// B bf16 (hi,lo) [N,*] row-stride ldb; K = reduction depth.
// LENMODE: 0 none; 1 proj (skip (row0%2048)>=len); 2 scores; 3 P.V (+ y-flip
//          so longest-K tiles launch first).
// OUTMODE: 0 fp32 C; 1 bf16 hi/lo split (row-major);
//          2 bf16 hi/lo split TRANSPOSED per batch -> Ch/Cl are [B][D][S]
// ---------------------------------------------------------------------------
#define ROWB 80
#define SM_TILE (128 * ROWB)            // 10240
#define STAGE_BYTES (4 * SM_TILE)       // 40960: Ah, Al, Bh, Bl
#define NSTAGE 4
#define SMEM_BYTES (NSTAGE * STAGE_BYTES)  // 163840
#define NTHR 256
#define TPAD 272                        // transpose-stage row stride (bytes)

template<bool SKIP_UPPER, bool CAUSAL_K, bool BIAS, int OUTMODE, int LENMODE>
__global__ void __launch_bounds__(NTHR, 1)
gemm_bf16x3(const __nv_bfloat16* __restrict__ Ah, const __nv_bfloat16* __restrict__ Al,
            const __nv_bfloat16* __restrict__ Bh, const __nv_bfloat16* __restrict__ Bl,
            const float* __restrict__ bias, float* __restrict__ C,
            __nv_bfloat16* __restrict__ Ch, __nv_bfloat16* __restrict__ Cl,
            int M, int N, int K, int lda, int ldb,
            long long sA, long long sB, long long sC, float alpha)
{
    if (SKIP_UPPER && blockIdx.x > blockIdx.y) return;

    int by = blockIdx.y;
    if (LENMODE == 3) by = gridDim.y - 1 - blockIdx.y;   // longest-K first

    const int row0 = by * 128;
    const int col0 = blockIdx.x * 128;

    int Keff = K;
    if (CAUSAL_K) { const int kl = (by + 1) * 128; Keff = kl < K ? kl : K; }

    if (LENMODE == 1) {
        const int b = row0 >> 11;
        if ((row0 & 2047) >= g_len[b]) return;
    } else if (LENMODE == 2) {
        const int L = g_len[blockIdx.z];
        if (row0 >= L || col0 >= L) return;
    } else if (LENMODE == 3) {
        const int L = g_len[blockIdx.z];
        if (row0 >= L) return;
        const int kcap = (L + 31) & ~31;
        if (kcap < Keff) Keff = kcap;
    }
    const int nchunk = Keff >> 5;   // K-chunk = 32

    extern __shared__ char smem[];

    const int tid = threadIdx.x;
    const int wid = tid >> 5, lane = tid & 31;
    const int wr = wid >> 2;        // 0..1  warp row (64 rows)
    const int wc = wid & 3;         // 0..3  warp col (32 cols)
    const int r4 = lane >> 2;
    const int c4 = lane & 3;

    Ah += (size_t)blockIdx.z * sA;  Al += (size_t)blockIdx.z * sA;
    Bh += (size_t)blockIdx.z * sB;  Bl += (size_t)blockIdx.z * sB;

    const uint32_t sb = smem_u32(smem);

    const int aRowSel = ((lane >> 3) & 1) * 8 + (lane & 7);
    const int aColSel = (lane >> 4) * 16;
    const int bRowSel = lane & 7;
    const int bColSel = ((lane >> 3) & 1) * 16;
    const uint32_t aBase = (uint32_t)((wr * 64 + aRowSel) * ROWB + aColSel);
    const uint32_t bBase = (uint32_t)((wc * 32 + bRowSel) * ROWB + bColSel);

    // loader: per tile, 2 cp.async of 16B per thread (128 rows x 64 B)
    auto ldstage = [&](int c, int s) {
        const long long kofs = (long long)c * 32;
        const uint32_t st = sb + s * STAGE_BYTES;
        const __nv_bfloat16* G[4] = { Ah, Al, Bh, Bl };
        #pragma unroll
        for (int t = 0; t < 4; t++) {
            const int r0 = (t < 2) ? row0 : col0;
            const int ld = (t < 2) ? lda : ldb;
            #pragma unroll
            for (int o = 0; o < 2; o++) {
                const int lin = tid + o * 256;
                const int row = lin >> 2;
                const int cb  = (lin & 3) * 16;
                const char* src = (const char*)G[t] + ((size_t)(r0 + row) * ld + kofs) * 2 + cb;
                cp_async16(st + t * SM_TILE + row * ROWB + cb, src);
            }
        }
        cp_commit();
    };

    float acc[4][4][4];
    #pragma unroll
    for (int i = 0; i < 4; i++)
        #pragma unroll
        for (int j = 0; j < 4; j++)
            #pragma unroll
            for (int r = 0; r < 4; r++) acc[i][j][r] = 0.0f;

    // prologue: fill up to 3 stages
    ldstage(0, 0);
    if (nchunk > 1) ldstage(1, 1); else cp_commit();
    if (nchunk > 2) ldstage(2, 2); else cp_commit();

    for (int c = 0; c < nchunk; c++) {
        if (c + 3 < nchunk) ldstage(c + 3, (c + 3) % NSTAGE);
        else cp_commit();                 // uniform group bookkeeping
        cp_wait<3>();
        __syncthreads();                  // stage c visible

        const uint32_t stg = sb + (c % NSTAGE) * STAGE_BYTES;
        #pragma unroll
        for (int ks = 0; ks < 2; ks++) {
            const uint32_t ko = ks * 32;

            uint32_t ah[4][4], al[4][4], bh[4][2], bl[4][2];
            #pragma unroll
            for (int nt = 0; nt < 4; nt++) {
                const uint32_t off = stg + bBase + nt * (8 * ROWB) + ko;
                ldsm_x2(bh[nt], off + 2 * SM_TILE);
                ldsm_x2(bl[nt], off + 3 * SM_TILE);
            }
            #pragma unroll
            for (int mt = 0; mt < 4; mt++) {
                const uint32_t off = stg + aBase + mt * (16 * ROWB) + ko;
                ldsm_x4(ah[mt], off);
                ldsm_x4(al[mt], off + SM_TILE);
            }

            #pragma unroll
            for (int mt = 0; mt < 4; mt++)
                #pragma unroll
                for (int nt = 0; nt < 4; nt++)
                    mma16816(acc[mt][nt], ah[mt], bh[nt]);
            #pragma unroll
            for (int mt = 0; mt < 4; mt++)
                #pragma unroll
                for (int nt = 0; nt < 4; nt++)
                    mma16816(acc[mt][nt], ah[mt], bl[nt]);
            #pragma unroll
            for (int mt = 0; mt < 4; mt++)
                #pragma unroll
                for (int nt = 0; nt < 4; nt++)
                    mma16816(acc[mt][nt], al[mt], bh[nt]);
        }
        __syncthreads();                  // before buffer reuse
    }

    // ---------------- epilogue ----------------
    if (OUTMODE == 2) {
        // Transposed bf16 hi/lo output via SMEM staging.
        #pragma unroll
        for (int mt = 0; mt < 4; mt++) {
            const int rl = wr * 64 + mt * 16 + r4;
            #pragma unroll
            for (int nt = 0; nt < 4; nt++) {
                const int cl = wc * 32 + nt * 8 + c4 * 2;
                const int cidx = col0 + cl;
                float b0 = 0.f, b1 = 0.f;
                if (BIAS) { b0 = __ldg(bias + cidx); b1 = __ldg(bias + cidx + 1); }
                const float v00 = alpha * acc[mt][nt][0] + b0;
                const float v01 = alpha * acc[mt][nt][1] + b1;
                const float v10 = alpha * acc[mt][nt][2] + b0;
                const float v11 = alpha * acc[mt][nt][3] + b1;
                __nv_bfloat16 h, l;
                split1(v00, h, l);
                *(__nv_bfloat16*)(smem + cl * TPAD + rl * 2) = h;
                *(__nv_bfloat16*)(smem + 128 * TPAD + cl * TPAD + rl * 2) = l;
                split1(v01, h, l);
                *(__nv_bfloat16*)(smem + (cl + 1) * TPAD + rl * 2) = h;
                *(__nv_bfloat16*)(smem + 128 * TPAD + (cl + 1) * TPAD + rl * 2) = l;
                split1(v10, h, l);
                *(__nv_bfloat16*)(smem + cl * TPAD + (rl + 8) * 2) = h;
                *(__nv_bfloat16*)(smem + 128 * TPAD + cl * TPAD + (rl + 8) * 2) = l;
                split1(v11, h, l);
                *(__nv_bfloat16*)(smem + (cl + 1) * TPAD + (rl + 8) * 2) = h;
                *(__nv_bfloat16*)(smem + 128 * TPAD + (cl + 1) * TPAD + (rl + 8) * 2) = l;
            }
        }
        __syncthreads();
        // coalesced write-out: thread -> (d-row, half); 64 elems = 128 B =
        // 8 x uint4 per thread per buffer.
        const int bidx = row0 >> 11;           // batch
        const int sloc = row0 & 2047;          // s offset within batch
        const int dl = tid >> 1;
        const int hf = tid & 1;
        __nv_bfloat16* oh = Ch + (size_t)bidx * DD * SS + (size_t)(col0 + dl) * SS + sloc + hf * 64;
        __nv_bfloat16* ol = Cl + (size_t)bidx * DD * SS + (size_t)(col0 + dl) * SS + sloc + hf * 64;
        const char* sh = smem + dl * TPAD + hf * 128;
        const char* sl = smem + 128 * TPAD + dl * TPAD + hf * 128;
        #pragma unroll
        for (int i = 0; i < 8; i++) {
            ((uint4*)oh)[i] = *(const uint4*)(sh + i * 16);
            ((uint4*)ol)[i] = *(const uint4*)(sl + i * 16);
        }
        return;
    }

    #pragma unroll
    for (int mt = 0; mt < 4; mt++) {
        const int r = row0 + wr * 64 + mt * 16 + r4;
        #pragma unroll
        for (int nt = 0; nt < 4; nt++) {
            const int cidx = col0 + wc * 32 + nt * 8 + c4 * 2;
            float b0 = 0.f, b1 = 0.f;
            if (BIAS) { b0 = __ldg(bias + cidx); b1 = __ldg(bias + cidx + 1); }
            const float v00 = alpha * acc[mt][nt][0] + b0;
            const float v01 = alpha * acc[mt][nt][1] + b1;
            const float v10 = alpha * acc[mt][nt][2] + b0;
            const float v11 = alpha * acc[mt][nt][3] + b1;
            if (OUTMODE == 1) {
                __nv_bfloat16 h0, l0, h1, l1;
                split1(v00, h0, l0); split1(v01, h1, l1);
                *(__nv_bfloat162*)(Ch + (size_t)r * N + cidx) = __nv_bfloat162(h0, h1);
                *(__nv_bfloat162*)(Cl + (size_t)r * N + cidx) = __nv_bfloat162(l0, l1);
                split1(v10, h0, l0); split1(v11, h1, l1);
                *(__nv_bfloat162*)(Ch + (size_t)(r + 8) * N + cidx) = __nv_bfloat162(h0, h1);
                *(__nv_bfloat162*)(Cl + (size_t)(r + 8) * N + cidx) = __nv_bfloat162(l0, l1);
            } else {
                float* Cz = C + (size_t)blockIdx.z * sC;
                *(float2*)(Cz + (size_t)r * N + cidx)       = make_float2(v00, v01);
                *(float2*)(Cz + (size_t)(r + 8) * N + cidx) = make_float2(v10, v11);
            }
        }
    }
}

// ---------------------------------------------------------------------------
// prep: per-batch lengths (block b) + combined bias (block 0)
// ---------------------------------------------------------------------------
__global__ void prep(const int* __restrict__ mask,
                     const float* __restrict__ bq, const float* __restrict__ bk)
{
    const int b = blockIdx.x;
    const int tid = threadIdx.x;
    if (b == 0) g_bqk[tid] = (tid < DKK) ? bq[tid] : bk[tid - DKK];
    __shared__ int red[256];
    int s = 0;
    for (int k = tid; k < SS; k += 256) s += mask[b * SS + k];
    red[tid] = s;
    __syncthreads();
    for (int o = 128; o > 0; o >>= 1) {
        if (tid < o) red[tid] += red[tid + o];
        __syncthreads();
    }
    if (tid == 0) g_len[b] = SS - red[0];
}

// ---------------------------------------------------------------------------
// FUSED: x split into bf16 hi/lo AND per-128-row column partial sums (same
// summation order as the previous x_colmean_part -> bit-identical xmean).
// Grid (DD/256, MTOT/128) = (4, 64); thread owns one column d for 128 rows.
// ---------------------------------------------------------------------------
__global__ void split_colmean(const float* __restrict__ x)
{
    const int d  = blockIdx.x * 256 + threadIdx.x;   // 0..1023
    const int rb = blockIdx.y;                       // 0..63 row block
    const size_t base = (size_t)rb * 128 * DD + d;
    float s = 0.0f;
    #pragma unroll 8
    for (int r = 0; r < 128; r++) {
        const size_t idx = base + (size_t)r * DD;
        const float v = x[idx];
        s += v;
        __nv_bfloat16 h, l;
        split1(v, h, l);
        g_xh[idx] = h;
        g_xl[idx] = l;
    }
    g_xpart[rb & 15][rb >> 4][d] = s;   // slice, batch
}
__global__ void x_colmean_finish()
{
    const int d = blockIdx.x * 256 + threadIdx.x;
    const int b = blockIdx.y;
    float s = 0.0f;
    #pragma unroll
    for (int sl = 0; sl < KSLICE; sl++) s += g_xpart[sl][b][d];
    g_xmean[b * DD + d] = s * (1.0f / (float)SS);
}

// ---------------------------------------------------------------------------
__global__ void vmean_part(const float* __restrict__ Wv)
{
    const int d = blockIdx.x * 256 + threadIdx.x;
    const int sl = blockIdx.y;
    float acc[BB] = {0.f, 0.f, 0.f, 0.f};
    #pragma unroll
    for (int kk = 0; kk < 16; kk++) {
        const int k = sl * 16 + kk;
        const float w = __ldg(Wv + (size_t)k * DD + d);
        #pragma unroll
        for (int b = 0; b < BB; b++) acc[b] += g_xmean[b * DD + k] * w;
    }
    #pragma unroll
    for (int b = 0; b < BB; b++) g_vpart[sl][b][d] = acc[b];
}
__global__ void vmean_finish(const float* __restrict__ bv)
{
    const int d = blockIdx.x * 256 + threadIdx.x;
    const int b = blockIdx.y;
    float s = __ldg(bv + d);
    #pragma unroll
    for (int sl = 0; sl < VSLICE; sl++) s += g_vpart[sl][b][d];
    g_vmean[b * DD + d] = s;
}

// ---------------------------------------------------------------------------
// fp32 [R,C] -> transposed bf16 hi/lo [C,R]; used for weights only.
// ---------------------------------------------------------------------------
__global__ void transpose_split(const float* __restrict__ in,
                                __nv_bfloat16* __restrict__ oh, __nv_bfloat16* __restrict__ ol,
                                int R, int C)
{
    const int c0 = blockIdx.x * 32, r0 = blockIdx.y * 32;
    __shared__ float t[32][33];
    const int tx = threadIdx.x & 31, ty = threadIdx.x >> 5;
    #pragma unroll
    for (int k = 0; k < 32; k += 8)
        t[ty + k][tx] = in[(size_t)(r0 + ty + k) * C + c0 + tx];
    __syncthreads();
    #pragma unroll
    for (int k = 0; k < 32; k += 8) {
        __nv_bfloat16 h, l;
        split1(t[tx][ty + k], h, l);
        oh[(size_t)(c0 + ty + k) * R + r0 + tx] = h;
        ol[(size_t)(c0 + ty + k) * R + r0 + tx] = l;
    }
}

// ---------------------------------------------------------------------------
__global__ void masked_softmax(const int* __restrict__ mask)
{
    const int q = blockIdx.x;
    const int b = blockIdx.y;
    if (mask[b * SS + q] != 0) return;

    const size_t off = ((size_t)b * SS + q) * SS;
    const float* row = g_s + off;
    __nv_bfloat16* ph = g_ph + off;
    __nv_bfloat16* pl = g_pl + off;
    const int tid = threadIdx.x;

    const int L   = g_len[b];
    const int cap = (L + 31) & ~31;

    __shared__ float red[256];

    float vals[8];
    float m = -INFINITY;
    #pragma unroll
    for (int it = 0; it < 8; it++) {
        const int k = tid + it * 256;
        float s = -INFINITY;
        if (k < cap) {
            const bool valid = (k <= q) && (mask[b * SS + k] == 0);
            s = valid ? row[k] : -INFINITY;
        }
        vals[it] = s;
        m = fmaxf(m, s);
    }
    red[tid] = m;
    __syncthreads();
    for (int o = 128; o > 0; o >>= 1) {
        if (tid < o) red[tid] = fmaxf(red[tid], red[tid + o]);
        __syncthreads();
    }
    m = red[0];
    __syncthreads();

    float sum = 0.0f;
    #pragma unroll
    for (int it = 0; it < 8; it++) {
        const float e = (vals[it] == -INFINITY) ? 0.0f : __expf(vals[it] - m);
        vals[it] = e;
        sum += e;
    }
    red[tid] = sum;
    __syncthreads();
    for (int o = 128; o > 0; o >>= 1) {
        if (tid < o) red[tid] += red[tid + o];
        __syncthreads();
    }
    const float inv = 1.0f / red[0];

    #pragma unroll
    for (int it = 0; it < 8; it++) {
        const int k = tid + it * 256;
        if (k < cap) {
            __nv_bfloat16 h, l;
            split1(vals[it] * inv, h, l);
            ph[k] = h;
            pl[k] = l;
        }
    }
}

// ---------------------------------------------------------------------------
__global__ void scatter_padded(const int* __restrict__ mask, float* __restrict__ out)
{
    const int q = blockIdx.x;
    const int b = blockIdx.y;
    if (mask[b * SS + q] == 0) return;
    const int tid = threadIdx.x;
    float* o = out + ((size_t)b * SS + q) * DD;
    const float* vm = g_vmean + b * DD;
    #pragma unroll
    for (int it = 0; it < 4; it++) o[tid + it * 256] = vm[tid + it * 256];
}

// ---------------------------------------------------------------------------
extern "C" void kernel_launch(void* const* d_in, const int* in_sizes, int n_in,
                              void* d_out, int out_size)
{
    const float* x    = (const float*)d_in[0];
    const int*   mask = (const int*)d_in[1];
    const float* Wq   = (const float*)d_in[2];
    const float* bq   = (const float*)d_in[3];
    const float* Wk   = (const float*)d_in[4];
    const float* bk   = (const float*)d_in[5];
    const float* Wv   = (const float*)d_in[6];
    const float* bv   = (const float*)d_in[7];
    float* out = (float*)d_out;

    cudaFuncSetAttribute(gemm_bf16x3<false, false, true, 1, 1>,
                         cudaFuncAttributeMaxDynamicSharedMemorySize, SMEM_BYTES);
    cudaFuncSetAttribute(gemm_bf16x3<false, false, true, 2, 1>,
                         cudaFuncAttributeMaxDynamicSharedMemorySize, SMEM_BYTES);
    cudaFuncSetAttribute(gemm_bf16x3<true, false, false, 0, 2>,
                         cudaFuncAttributeMaxDynamicSharedMemorySize, SMEM_BYTES);
    cudaFuncSetAttribute(gemm_bf16x3<false, true, false, 0, 3>,
                         cudaFuncAttributeMaxDynamicSharedMemorySize, SMEM_BYTES);

    __nv_bfloat16 *xh, *xl, *wqkth, *wqktl, *wvth, *wvtl;
    __nv_bfloat16 *qkh, *qkl, *vth, *vtl, *ph, *pl;
    float *s, *bqk;
    cudaGetSymbolAddress((void**)&xh, g_xh);      cudaGetSymbolAddress((void**)&xl, g_xl);
    cudaGetSymbolAddress((void**)&wqkth, g_wqkt_h); cudaGetSymbolAddress((void**)&wqktl, g_wqkt_l);
    cudaGetSymbolAddress((void**)&wvth, g_wvt_h); cudaGetSymbolAddress((void**)&wvtl, g_wvt_l);
    cudaGetSymbolAddress((void**)&qkh, g_qkh);    cudaGetSymbolAddress((void**)&qkl, g_qkl);
    cudaGetSymbolAddress((void**)&vth, g_vth);    cudaGetSymbolAddress((void**)&vtl, g_vtl);
    cudaGetSymbolAddress((void**)&s, g_s);
    cudaGetSymbolAddress((void**)&ph, g_ph);      cudaGetSymbolAddress((void**)&pl, g_pl);
    cudaGetSymbolAddress((void**)&bqk, g_bqk);

    const float scale = 1.0f / sqrtf((float)DKK);

    // 0. lengths + combined bias; fused x split + column partials; means
    prep<<<BB, 256>>>(mask, bq, bk);
    split_colmean<<<dim3(DD / 256, MTOT / 128), 256>>>(x);
    x_colmean_finish<<<dim3(DD / 256, BB), 256>>>();
    vmean_part<<<dim3(DD / 256, VSLICE), 256>>>(Wv);
    vmean_finish<<<dim3(DD / 256, BB), 256>>>(bv);

    // 1. transpose + split weights.  Wq -> rows 0..127 of WqkT, Wk -> 128..255
    transpose_split<<<dim3(DKK / 32, DD / 32, 1), 256>>>(Wq, wqkth, wqktl, DD, DKK);
    transpose_split<<<dim3(DKK / 32, DD / 32, 1), 256>>>(Wk, wqkth + (size_t)DKK * DD,
                                                         wqktl + (size_t)DKK * DD, DD, DKK);
    transpose_split<<<dim3(DD / 32, DD / 32, 1), 256>>>(Wv, wvth, wvtl, DD, DD);

    // 2a. fused q|k projection: [8192, 256] = x @ [Wq|Wk]
    gemm_bf16x3<false, false, true, 1, 1><<<dim3(2 * DKK / 128, MTOT / 128, 1), NTHR, SMEM_BYTES>>>(
        xh, xl, wqkth, wqktl, bqk, nullptr, qkh, qkl,
        MTOT, 2 * DKK, DD, DD, DD, 0, 0, 0, 1.0f);
    // 2b. v projection -> TRANSPOSED bf16 hi/lo [B][D][S] directly
    gemm_bf16x3<false, false, true, 2, 1><<<dim3(DD / 128, MTOT / 128, 1), NTHR, SMEM_BYTES>>>(
        xh, xl, wvth, wvtl, bv, nullptr, vth, vtl,
        MTOT, DD, DD, DD, DD, 0, 0, 0, 1.0f);

    // 3. scores = q @ k^T from the combined buffer, lower-triangle clipped
    gemm_bf16x3<true, false, false, 0, 2><<<dim3(SS / 128, SS / 128, BB), NTHR, SMEM_BYTES>>>(
        qkh, qkl, qkh + DKK, qkl + DKK, nullptr, s, nullptr, nullptr,
        SS, SS, DKK, 2 * DKK, 2 * DKK,
        (long long)SS * 2 * DKK, (long long)SS * 2 * DKK, (long long)SS * SS, scale);

    // 4. masked softmax -> P (bf16 hi/lo), bounded to round_up(len,32)
    masked_softmax<<<dim3(SS, BB), 256>>>(mask);

    // 5. out = P @ V^T-layout, K truncated to min(causal, len); skip rows>=len;
    //    longest-K tiles launch first
    gemm_bf16x3<false, true, false, 0, 3><<<dim3(DD / 128, SS / 128, BB), NTHR, SMEM_BYTES>>>(
        ph, pl, vth, vtl, nullptr, out, nullptr, nullptr,
        SS, DD, SS, SS, SS,
        (long long)SS * SS, (long long)DD * SS, (long long)SS * DD, 1.0f);

    // 6. padded rows <- uniform attention
    scatter_padded<<<dim3(SS, BB), 256>>>(mask, out);
}